// round 6
// baseline (speedup 1.0000x reference)
#include <cuda_runtime.h>
#include <cuda_bf16.h>
#include <math.h>
#include <stdint.h>

// Problem shape constants (fixed by the dataset)
#define NMAX 40000
#define EMAX 640000
#define D    128
#define HID  512

// ---------------- scratch (static device allocations; no cudaMalloc) --------
__device__ float    g_q[NMAX * D];
__device__ uint32_t g_kb[NMAX * (D / 2)];   // k in bf16x2
__device__ uint32_t g_vb[NMAX * (D / 2)];   // v in bf16x2
__device__ float    g_agg[NMAX * D];
__device__ float    g_ln[NMAX * D];
__device__ float    g_hidden[NMAX * HID];
__device__ int      g_deg[NMAX];
__device__ int      g_cursor[NMAX];
__device__ int      g_rowptr[NMAX + 1];
__device__ int      g_colsrc[EMAX];

// ---------------- CSR build --------------------------------------------------
__global__ void zero_deg_kernel(int n) {
    int i = blockIdx.x * blockDim.x + threadIdx.x;
    if (i < n) g_deg[i] = 0;
}

__global__ void hist_kernel(const int* __restrict__ ei, int E) {
    int e = blockIdx.x * blockDim.x + threadIdx.x;
    if (e < E) atomicAdd(&g_deg[ei[E + e]], 1);
}

// single-block exclusive scan over g_deg -> g_rowptr, g_cursor
__global__ __launch_bounds__(1024)
void scan_kernel(int n) {
    __shared__ int warpsums[32];
    const int T = 1024;
    int tid  = threadIdx.x;
    int lane = tid & 31, wid = tid >> 5;
    int per = (n + T - 1) / T;
    int start = tid * per;
    int end   = min(start + per, n);
    int sum = 0;
    for (int i = start; i < end; i++) sum += g_deg[i];
    int v = sum;
    #pragma unroll
    for (int off = 1; off < 32; off <<= 1) {
        int t = __shfl_up_sync(0xffffffffu, v, off);
        if (lane >= off) v += t;
    }
    if (lane == 31) warpsums[wid] = v;
    __syncthreads();
    if (wid == 0) {
        int w = warpsums[lane];
        #pragma unroll
        for (int off = 1; off < 32; off <<= 1) {
            int t = __shfl_up_sync(0xffffffffu, w, off);
            if (lane >= off) w += t;
        }
        warpsums[lane] = w;
    }
    __syncthreads();
    int offset = (wid > 0 ? warpsums[wid - 1] : 0) + v - sum;  // exclusive prefix
    int run = offset;
    for (int i = start; i < end; i++) {
        g_rowptr[i] = run;
        g_cursor[i] = run;
        run += g_deg[i];
    }
    if (end == n) g_rowptr[n] = run;
}

__global__ void scatter_kernel(const int* __restrict__ ei, int E) {
    int e = blockIdx.x * blockDim.x + threadIdx.x;
    if (e < E) {
        int dst = ei[E + e];
        int pos = atomicAdd(&g_cursor[dst], 1);
        g_colsrc[pos] = ei[e];   // src
    }
}

// ---------------- node-centric attention aggregation (warp per node) --------
// agg[node] = ( sum_e exp(q[node]·k[src]/sqrt(32)) * v[src] ) / sum_e exp(...)
// Scores std ~0.05 -> softmax without max-subtract is safe.
__global__ __launch_bounds__(256)
void node_agg_kernel(int Nn) {
    int node = blockIdx.x * 8 + (threadIdx.x >> 5);
    int lane = threadIdx.x & 31;
    if (node >= Nn) return;

    float4 qv = reinterpret_cast<const float4*>(g_q + (size_t)node * D)[lane];
    float m0 = 0.f, m1 = 0.f, m2 = 0.f, m3 = 0.f, exsum = 0.f;

    int beg = g_rowptr[node], end = g_rowptr[node + 1];
    for (int p = beg; p < end; p++) {
        int src = g_colsrc[p];
        uint2 kp = reinterpret_cast<const uint2*>(g_kb)[(size_t)src * 32 + lane];
        uint2 vp = reinterpret_cast<const uint2*>(g_vb)[(size_t)src * 32 + lane];
        float2 ka = __bfloat1622float2(*reinterpret_cast<__nv_bfloat162*>(&kp.x));
        float2 kc = __bfloat1622float2(*reinterpret_cast<__nv_bfloat162*>(&kp.y));
        float pd = qv.x * ka.x + qv.y * ka.y + qv.z * kc.x + qv.w * kc.y;
        pd += __shfl_xor_sync(0xffffffffu, pd, 4);
        pd += __shfl_xor_sync(0xffffffffu, pd, 2);
        pd += __shfl_xor_sync(0xffffffffu, pd, 1);
        float ex = __expf(pd * 0.17677669529663687f);  // 1/sqrt(32)
        exsum += ex;
        float2 va = __bfloat1622float2(*reinterpret_cast<__nv_bfloat162*>(&vp.x));
        float2 vc = __bfloat1622float2(*reinterpret_cast<__nv_bfloat162*>(&vp.y));
        m0 += ex * va.x; m1 += ex * va.y; m2 += ex * vc.x; m3 += ex * vc.y;
    }
    float rcp = exsum > 0.f ? __frcp_rn(exsum) : 0.f;
    reinterpret_cast<float4*>(g_agg + (size_t)node * D)[lane] =
        make_float4(m0 * rcp, m1 * rcp, m2 * rcp, m3 * rcp);
}

// ---------------- fast GELU (tanh form via expf) -----------------------------
__device__ __forceinline__ float gelu_tanh(float x) {
    float u = 0.7978845608028654f * (x + 0.044715f * x * x * x);
    float e = __expf(2.f * u);
    return x * e / (e + 1.f);
}

// ---------------- tf32 conversion -------------------------------------------
__device__ __forceinline__ uint32_t f2tf32(float f) {
    uint32_t r;
    asm("cvt.rna.tf32.f32 %0, %1;" : "=r"(r) : "f"(f));
    return r;
}

#define ASTRIDE 20
#define BSTRIDE 132

// ---------------- generic tf32 GEMM body ------------------------------------
// EPI: 0=none, 1=gelu, 2=+residual.  BF16OUT: pack output to bf16x2.
template <int EPI, bool BF16OUT>
__device__ __forceinline__
void gemm_body(const float* __restrict__ A, const float* __restrict__ B,
               const float* __restrict__ bias, const float* __restrict__ res,
               float* __restrict__ C, int M, int N, int K) {
    __shared__ float As[2][128 * ASTRIDE];
    __shared__ float Bs[2][16 * BSTRIDE];

    const int tid  = threadIdx.x;
    const int lane = tid & 31;
    const int wid  = tid >> 5;
    const int bm   = blockIdx.x * 128;
    const int bn   = blockIdx.y * 128;
    const int wm   = (wid & 3) * 32;
    const int wn   = (wid >> 2) * 64;

    const int a_row  = tid >> 2;
    const int a_col  = (tid & 3) * 4;
    const int b_row  = tid >> 5;
    const int b_col  = (tid & 31) * 4;

    const int ar0 = min(bm + a_row,      M - 1);
    const int ar1 = min(bm + a_row + 64, M - 1);

    float acc[2][8][4];
    #pragma unroll
    for (int i = 0; i < 2; i++)
        #pragma unroll
        for (int j = 0; j < 8; j++)
            #pragma unroll
            for (int c = 0; c < 4; c++) acc[i][j][c] = 0.f;

    float4 a_reg0 = *reinterpret_cast<const float4*>(A + (size_t)ar0 * K + a_col);
    float4 a_reg1 = *reinterpret_cast<const float4*>(A + (size_t)ar1 * K + a_col);
    float4 b_reg0 = *reinterpret_cast<const float4*>(B + (size_t)b_row * N + bn + b_col);
    float4 b_reg1 = *reinterpret_cast<const float4*>(B + (size_t)(b_row + 8) * N + bn + b_col);

    const int nIter = K >> 4;
    for (int it = 0; it < nIter; it++) {
        const int cur = it & 1;
        float* pa0 = &As[cur][a_row * ASTRIDE + a_col];
        pa0[0] = __uint_as_float(f2tf32(a_reg0.x));
        pa0[1] = __uint_as_float(f2tf32(a_reg0.y));
        pa0[2] = __uint_as_float(f2tf32(a_reg0.z));
        pa0[3] = __uint_as_float(f2tf32(a_reg0.w));
        float* pa1 = &As[cur][(a_row + 64) * ASTRIDE + a_col];
        pa1[0] = __uint_as_float(f2tf32(a_reg1.x));
        pa1[1] = __uint_as_float(f2tf32(a_reg1.y));
        pa1[2] = __uint_as_float(f2tf32(a_reg1.z));
        pa1[3] = __uint_as_float(f2tf32(a_reg1.w));
        float* pb0 = &Bs[cur][b_row * BSTRIDE + b_col];
        pb0[0] = __uint_as_float(f2tf32(b_reg0.x));
        pb0[1] = __uint_as_float(f2tf32(b_reg0.y));
        pb0[2] = __uint_as_float(f2tf32(b_reg0.z));
        pb0[3] = __uint_as_float(f2tf32(b_reg0.w));
        float* pb1 = &Bs[cur][(b_row + 8) * BSTRIDE + b_col];
        pb1[0] = __uint_as_float(f2tf32(b_reg1.x));
        pb1[1] = __uint_as_float(f2tf32(b_reg1.y));
        pb1[2] = __uint_as_float(f2tf32(b_reg1.z));
        pb1[3] = __uint_as_float(f2tf32(b_reg1.w));
        __syncthreads();

        if (it + 1 < nIter) {
            int kn = (it + 1) << 4;
            a_reg0 = *reinterpret_cast<const float4*>(A + (size_t)ar0 * K + kn + a_col);
            a_reg1 = *reinterpret_cast<const float4*>(A + (size_t)ar1 * K + kn + a_col);
            b_reg0 = *reinterpret_cast<const float4*>(B + (size_t)(kn + b_row) * N + bn + b_col);
            b_reg1 = *reinterpret_cast<const float4*>(B + (size_t)(kn + b_row + 8) * N + bn + b_col);
        }

        #pragma unroll
        for (int ks = 0; ks < 16; ks += 8) {
            uint32_t af[2][4];
            #pragma unroll
            for (int i = 0; i < 2; i++) {
                int m = wm + i * 16 + (lane >> 2);
                int c = ks + (lane & 3);
                af[i][0] = __float_as_uint(As[cur][m * ASTRIDE + c]);
                af[i][1] = __float_as_uint(As[cur][(m + 8) * ASTRIDE + c]);
                af[i][2] = __float_as_uint(As[cur][m * ASTRIDE + c + 4]);
                af[i][3] = __float_as_uint(As[cur][(m + 8) * ASTRIDE + c + 4]);
            }
            uint32_t bf[8][2];
            #pragma unroll
            for (int j = 0; j < 8; j++) {
                int n = wn + j * 8 + (lane >> 2);
                int r = ks + (lane & 3);
                bf[j][0] = __float_as_uint(Bs[cur][r * BSTRIDE + n]);
                bf[j][1] = __float_as_uint(Bs[cur][(r + 4) * BSTRIDE + n]);
            }
            #pragma unroll
            for (int i = 0; i < 2; i++)
                #pragma unroll
                for (int j = 0; j < 8; j++) {
                    asm volatile(
                        "mma.sync.aligned.m16n8k8.row.col.f32.tf32.tf32.f32 "
                        "{%0,%1,%2,%3}, {%4,%5,%6,%7}, {%8,%9}, {%0,%1,%2,%3};"
                        : "+f"(acc[i][j][0]), "+f"(acc[i][j][1]),
                          "+f"(acc[i][j][2]), "+f"(acc[i][j][3])
                        : "r"(af[i][0]), "r"(af[i][1]), "r"(af[i][2]), "r"(af[i][3]),
                          "r"(bf[j][0]), "r"(bf[j][1]));
                }
        }
    }

    uint32_t* Cb = reinterpret_cast<uint32_t*>(C);
    #pragma unroll
    for (int i = 0; i < 2; i++) {
        int r0 = bm + wm + i * 16 + (lane >> 2);
        int r1 = r0 + 8;
        #pragma unroll
        for (int j = 0; j < 8; j++) {
            int c = bn + wn + j * 8 + (lane & 3) * 2;
            float b0 = bias[c], b1 = bias[c + 1];
            float v00 = acc[i][j][0] + b0, v01 = acc[i][j][1] + b1;
            float v10 = acc[i][j][2] + b0, v11 = acc[i][j][3] + b1;
            if (EPI == 1) {
                v00 = gelu_tanh(v00); v01 = gelu_tanh(v01);
                v10 = gelu_tanh(v10); v11 = gelu_tanh(v11);
            }
            if (r0 < M) {
                if (EPI == 2) {
                    float2 rv = *reinterpret_cast<const float2*>(res + (size_t)r0 * N + c);
                    v00 += rv.x; v01 += rv.y;
                }
                if (BF16OUT) {
                    __nv_bfloat162 h = __float22bfloat162_rn(make_float2(v00, v01));
                    Cb[(size_t)r0 * (N >> 1) + (c >> 1)] = *reinterpret_cast<uint32_t*>(&h);
                } else {
                    *reinterpret_cast<float2*>(C + (size_t)r0 * N + c) = make_float2(v00, v01);
                }
            }
            if (r1 < M) {
                if (EPI == 2) {
                    float2 rv = *reinterpret_cast<const float2*>(res + (size_t)r1 * N + c);
                    v10 += rv.x; v11 += rv.y;
                }
                if (BF16OUT) {
                    __nv_bfloat162 h = __float22bfloat162_rn(make_float2(v10, v11));
                    Cb[(size_t)r1 * (N >> 1) + (c >> 1)] = *reinterpret_cast<uint32_t*>(&h);
                } else {
                    *reinterpret_cast<float2*>(C + (size_t)r1 * N + c) = make_float2(v10, v11);
                }
            }
        }
    }
}

template <int EPI>
__global__ __launch_bounds__(256, 2)
void mma_gemm_kernel(const float* __restrict__ A, const float* __restrict__ B,
                     const float* __restrict__ bias, const float* __restrict__ res,
                     float* __restrict__ C, int M, int N, int K) {
    gemm_body<EPI, false>(A, B, bias, res, C, M, N, K);
}

// fused Q/K/V projection: z=0 -> q (fp32), z=1 -> k (bf16), z=2 -> v (bf16)
__global__ __launch_bounds__(256, 2)
void mma_gemm_qkv_kernel(const float* __restrict__ A,
                         const float* __restrict__ Wq, const float* __restrict__ Wk,
                         const float* __restrict__ Wv,
                         const float* __restrict__ bq, const float* __restrict__ bk,
                         const float* __restrict__ bv,
                         float* q, int M) {
    int z = blockIdx.z;
    if (z == 0) {
        gemm_body<0, false>(A, Wq, bq, nullptr, q, M, D, D);
    } else if (z == 1) {
        gemm_body<0, true>(A, Wk, bk, nullptr, reinterpret_cast<float*>(g_kb), M, D, D);
    } else {
        gemm_body<0, true>(A, Wv, bv, nullptr, reinterpret_cast<float*>(g_vb), M, D, D);
    }
}

// ---------------- fused Wo GEMM: + residual + LayerNorm ---------------------
// C_ln = LayerNorm( agg @ Wo + bo + x ) ; K = N = 128 fixed.
__global__ __launch_bounds__(256, 2)
void mma_gemm_wo_ln_kernel(const float* __restrict__ A,
                           const float* __restrict__ Bw,
                           const float* __restrict__ bias,
                           const float* __restrict__ x,
                           const float* __restrict__ lng,
                           const float* __restrict__ lnb,
                           float* __restrict__ C, int M) {
    __shared__ float As[2][128 * ASTRIDE];
    __shared__ float Bs[2][16 * BSTRIDE];
    __shared__ float row_s[128];
    __shared__ float row_sq[128];

    const int tid  = threadIdx.x;
    const int lane = tid & 31;
    const int wid  = tid >> 5;
    const int bm   = blockIdx.x * 128;
    const int wm   = (wid & 3) * 32;
    const int wn   = (wid >> 2) * 64;

    const int a_row  = tid >> 2;
    const int a_col  = (tid & 3) * 4;
    const int b_row  = tid >> 5;
    const int b_col  = (tid & 31) * 4;

    const int ar0 = min(bm + a_row,      M - 1);
    const int ar1 = min(bm + a_row + 64, M - 1);

    if (tid < 128) { row_s[tid] = 0.f; row_sq[tid] = 0.f; }

    float acc[2][8][4];
    #pragma unroll
    for (int i = 0; i < 2; i++)
        #pragma unroll
        for (int j = 0; j < 8; j++)
            #pragma unroll
            for (int c = 0; c < 4; c++) acc[i][j][c] = 0.f;

    float4 a_reg0 = *reinterpret_cast<const float4*>(A + (size_t)ar0 * D + a_col);
    float4 a_reg1 = *reinterpret_cast<const float4*>(A + (size_t)ar1 * D + a_col);
    float4 b_reg0 = *reinterpret_cast<const float4*>(Bw + (size_t)b_row * D + b_col);
    float4 b_reg1 = *reinterpret_cast<const float4*>(Bw + (size_t)(b_row + 8) * D + b_col);

    #pragma unroll
    for (int it = 0; it < 8; it++) {
        const int cur = it & 1;
        float* pa0 = &As[cur][a_row * ASTRIDE + a_col];
        pa0[0] = __uint_as_float(f2tf32(a_reg0.x));
        pa0[1] = __uint_as_float(f2tf32(a_reg0.y));
        pa0[2] = __uint_as_float(f2tf32(a_reg0.z));
        pa0[3] = __uint_as_float(f2tf32(a_reg0.w));
        float* pa1 = &As[cur][(a_row + 64) * ASTRIDE + a_col];
        pa1[0] = __uint_as_float(f2tf32(a_reg1.x));
        pa1[1] = __uint_as_float(f2tf32(a_reg1.y));
        pa1[2] = __uint_as_float(f2tf32(a_reg1.z));
        pa1[3] = __uint_as_float(f2tf32(a_reg1.w));
        float* pb0 = &Bs[cur][b_row * BSTRIDE + b_col];
        pb0[0] = __uint_as_float(f2tf32(b_reg0.x));
        pb0[1] = __uint_as_float(f2tf32(b_reg0.y));
        pb0[2] = __uint_as_float(f2tf32(b_reg0.z));
        pb0[3] = __uint_as_float(f2tf32(b_reg0.w));
        float* pb1 = &Bs[cur][(b_row + 8) * BSTRIDE + b_col];
        pb1[0] = __uint_as_float(f2tf32(b_reg1.x));
        pb1[1] = __uint_as_float(f2tf32(b_reg1.y));
        pb1[2] = __uint_as_float(f2tf32(b_reg1.z));
        pb1[3] = __uint_as_float(f2tf32(b_reg1.w));
        __syncthreads();

        if (it + 1 < 8) {
            int kn = (it + 1) << 4;
            a_reg0 = *reinterpret_cast<const float4*>(A + (size_t)ar0 * D + kn + a_col);
            a_reg1 = *reinterpret_cast<const float4*>(A + (size_t)ar1 * D + kn + a_col);
            b_reg0 = *reinterpret_cast<const float4*>(Bw + (size_t)(kn + b_row) * D + b_col);
            b_reg1 = *reinterpret_cast<const float4*>(Bw + (size_t)(kn + b_row + 8) * D + b_col);
        }

        #pragma unroll
        for (int ks = 0; ks < 16; ks += 8) {
            uint32_t af[2][4];
            #pragma unroll
            for (int i = 0; i < 2; i++) {
                int m = wm + i * 16 + (lane >> 2);
                int c = ks + (lane & 3);
                af[i][0] = __float_as_uint(As[cur][m * ASTRIDE + c]);
                af[i][1] = __float_as_uint(As[cur][(m + 8) * ASTRIDE + c]);
                af[i][2] = __float_as_uint(As[cur][m * ASTRIDE + c + 4]);
                af[i][3] = __float_as_uint(As[cur][(m + 8) * ASTRIDE + c + 4]);
            }
            uint32_t bf[8][2];
            #pragma unroll
            for (int j = 0; j < 8; j++) {
                int n = wn + j * 8 + (lane >> 2);
                int r = ks + (lane & 3);
                bf[j][0] = __float_as_uint(Bs[cur][r * BSTRIDE + n]);
                bf[j][1] = __float_as_uint(Bs[cur][(r + 4) * BSTRIDE + n]);
            }
            #pragma unroll
            for (int i = 0; i < 2; i++)
                #pragma unroll
                for (int j = 0; j < 8; j++) {
                    asm volatile(
                        "mma.sync.aligned.m16n8k8.row.col.f32.tf32.tf32.f32 "
                        "{%0,%1,%2,%3}, {%4,%5,%6,%7}, {%8,%9}, {%0,%1,%2,%3};"
                        : "+f"(acc[i][j][0]), "+f"(acc[i][j][1]),
                          "+f"(acc[i][j][2]), "+f"(acc[i][j][3])
                        : "r"(af[i][0]), "r"(af[i][1]), "r"(af[i][2]), "r"(af[i][3]),
                          "r"(bf[j][0]), "r"(bf[j][1]));
                }
        }
    }

    // epilogue: bias + residual, per-row LN stats via smem atomics
    #pragma unroll
    for (int i = 0; i < 2; i++) {
        int lr0 = wm + i * 16 + (lane >> 2);
        int lr1 = lr0 + 8;
        int r0 = bm + lr0, r1 = bm + lr1;
        float s0 = 0.f, q0 = 0.f, s1 = 0.f, q1 = 0.f;
        #pragma unroll
        for (int j = 0; j < 8; j++) {
            int c = wn + j * 8 + (lane & 3) * 2;
            float b0 = bias[c], b1 = bias[c + 1];
            if (r0 < M) {
                float2 rv = *reinterpret_cast<const float2*>(x + (size_t)r0 * D + c);
                acc[i][j][0] += b0 + rv.x;
                acc[i][j][1] += b1 + rv.y;
                s0 += acc[i][j][0] + acc[i][j][1];
                q0 += acc[i][j][0] * acc[i][j][0] + acc[i][j][1] * acc[i][j][1];
            }
            if (r1 < M) {
                float2 rv = *reinterpret_cast<const float2*>(x + (size_t)r1 * D + c);
                acc[i][j][2] += b0 + rv.x;
                acc[i][j][3] += b1 + rv.y;
                s1 += acc[i][j][2] + acc[i][j][3];
                q1 += acc[i][j][2] * acc[i][j][2] + acc[i][j][3] * acc[i][j][3];
            }
        }
        if (r0 < M) { atomicAdd(&row_s[lr0], s0); atomicAdd(&row_sq[lr0], q0); }
        if (r1 < M) { atomicAdd(&row_s[lr1], s1); atomicAdd(&row_sq[lr1], q1); }
    }
    __syncthreads();
    if (tid < 128) {
        float mu  = row_s[tid] * (1.f / 128.f);
        float var = row_sq[tid] * (1.f / 128.f) - mu * mu;
        row_s[tid]  = mu;
        row_sq[tid] = rsqrtf(var + 1e-5f);
    }
    __syncthreads();

    #pragma unroll
    for (int i = 0; i < 2; i++) {
        int lr0 = wm + i * 16 + (lane >> 2);
        int lr1 = lr0 + 8;
        int r0 = bm + lr0, r1 = bm + lr1;
        float mu0 = row_s[lr0], rs0 = row_sq[lr0];
        float mu1 = row_s[lr1], rs1 = row_sq[lr1];
        #pragma unroll
        for (int j = 0; j < 8; j++) {
            int c = wn + j * 8 + (lane & 3) * 2;
            float g0 = lng[c], g1 = lng[c + 1];
            float bb0 = lnb[c], bb1 = lnb[c + 1];
            if (r0 < M) {
                float v0 = (acc[i][j][0] - mu0) * rs0 * g0 + bb0;
                float v1 = (acc[i][j][1] - mu0) * rs0 * g1 + bb1;
                *reinterpret_cast<float2*>(C + (size_t)r0 * D + c) = make_float2(v0, v1);
            }
            if (r1 < M) {
                float v0 = (acc[i][j][2] - mu1) * rs1 * g0 + bb0;
                float v1 = (acc[i][j][3] - mu1) * rs1 * g1 + bb1;
                *reinterpret_cast<float2*>(C + (size_t)r1 * D + c) = make_float2(v0, v1);
            }
        }
    }
}

// ---------------- launch ----------------------------------------------------
extern "C" void kernel_launch(void* const* d_in, const int* in_sizes, int n_in,
                              void* d_out, int out_size) {
    const float* x   = (const float*)d_in[0];
    const int*   ei  = (const int*)d_in[1];   // int32 (JAX x64 disabled)
    const float* Wq  = (const float*)d_in[2];
    const float* bq  = (const float*)d_in[3];
    const float* Wk  = (const float*)d_in[4];
    const float* bk  = (const float*)d_in[5];
    const float* Wv  = (const float*)d_in[6];
    const float* bv  = (const float*)d_in[7];
    const float* Wo  = (const float*)d_in[8];
    const float* bo  = (const float*)d_in[9];
    const float* lng = (const float*)d_in[10];
    const float* lnb = (const float*)d_in[11];
    const float* W1  = (const float*)d_in[12];
    const float* b1  = (const float*)d_in[13];
    const float* W2  = (const float*)d_in[14];
    const float* b2  = (const float*)d_in[15];

    int N = in_sizes[0] / D;   // 40000
    int E = in_sizes[1] / 2;   // 640000

    void *pq, *pagg, *pln, *phid;
    cudaGetSymbolAddress(&pq,   g_q);
    cudaGetSymbolAddress(&pagg, g_agg);
    cudaGetSymbolAddress(&pln,  g_ln);
    cudaGetSymbolAddress(&phid, g_hidden);

    float* q   = (float*)pq;
    float* agg = (float*)pagg;
    float* ln  = (float*)pln;
    float* hid = (float*)phid;

    int mb = (N + 127) / 128;          // 313 row blocks
    int eb = (E + 255) / 256;

    // 1. CSR build (by destination)
    zero_deg_kernel<<<(N + 255) / 256, 256>>>(N);
    hist_kernel<<<eb, 256>>>(ei, E);
    scan_kernel<<<1, 1024>>>(N);
    scatter_kernel<<<eb, 256>>>(ei, E);

    // 2. fused q/k/v projections (k, v written as bf16)
    dim3 gQKV(mb, 1, 3);
    mma_gemm_qkv_kernel<<<gQKV, 256>>>(x, Wq, Wk, Wv, bq, bk, bv, q, N);

    // 3. node-centric attention aggregation (no atomics, normalized in-kernel)
    node_agg_kernel<<<(N + 7) / 8, 256>>>(N);

    // 4. fused: Wo projection + residual + LayerNorm -> g_ln
    mma_gemm_wo_ln_kernel<<<mb, 256>>>(agg, Wo, bo, x, lng, lnb, ln, N);

    // 5. MLP: gelu(ln @ W1 + b1) @ W2 + b2 + ln  -> d_out
    dim3 gH(mb, HID / 128);
    dim3 gD(mb, 1);
    mma_gemm_kernel<1><<<gH, 256>>>(ln, W1, b1, nullptr, hid, N, HID, D);
    mma_gemm_kernel<2><<<gD, 256>>>(hid, W2, b2, ln, (float*)d_out, N, D, HID);
}

// round 7
// speedup vs baseline: 1.0524x; 1.0524x over previous
#include <cuda_runtime.h>
#include <cuda_bf16.h>
#include <math.h>
#include <stdint.h>

// Problem shape constants (fixed by the dataset)
#define NMAX 40000
#define EMAX 640000
#define D    128
#define HID  512

// ---------------- scratch (static device allocations; no cudaMalloc) --------
__device__ uint32_t g_qb[NMAX * (D / 2)];   // q in bf16x2
__device__ uint32_t g_kb[NMAX * (D / 2)];   // k in bf16x2
__device__ uint32_t g_vb[NMAX * (D / 2)];   // v in bf16x2
__device__ float    g_segsum[NMAX * 4];
__device__ float    g_agg[NMAX * D];
__device__ float    g_ln[NMAX * D];
__device__ uint32_t g_hidden[NMAX * (HID / 2)];  // hidden in bf16x2

// ---------------- init: zero accumulators (vectorized) ----------------------
__global__ void init_kernel(int n) {
    int i = blockIdx.x * blockDim.x + threadIdx.x;
    if (i < n * (D / 4)) reinterpret_cast<float4*>(g_agg)[i] =
        make_float4(0.f, 0.f, 0.f, 0.f);
    if (i < n) reinterpret_cast<float4*>(g_segsum)[i] =
        make_float4(0.f, 0.f, 0.f, 0.f);
}

// ---------------- fused edge pass (bf16 gathers) -----------------------------
// Scores have std ~0.05 -> softmax without max-subtract is safe (shift-inv).
__global__ void edge_fused_kernel(const int* __restrict__ ei, int E) {
    int e    = (blockIdx.x * blockDim.x + threadIdx.x) >> 5;
    int lane = threadIdx.x & 31;
    if (e >= E) return;
    size_t src = (size_t)ei[e];
    size_t dst = (size_t)ei[(size_t)E + e];

    uint2 qp = reinterpret_cast<const uint2*>(g_qb)[dst * 32 + lane];
    uint2 kp = reinterpret_cast<const uint2*>(g_kb)[src * 32 + lane];
    float2 qa = __bfloat1622float2(*reinterpret_cast<__nv_bfloat162*>(&qp.x));
    float2 qc = __bfloat1622float2(*reinterpret_cast<__nv_bfloat162*>(&qp.y));
    float2 ka = __bfloat1622float2(*reinterpret_cast<__nv_bfloat162*>(&kp.x));
    float2 kc = __bfloat1622float2(*reinterpret_cast<__nv_bfloat162*>(&kp.y));
    float p = qa.x * ka.x + qa.y * ka.y + qc.x * kc.x + qc.y * kc.y;
    p += __shfl_xor_sync(0xffffffffu, p, 4);
    p += __shfl_xor_sync(0xffffffffu, p, 2);
    p += __shfl_xor_sync(0xffffffffu, p, 1);
    float ex = __expf(p * 0.17677669529663687f);  // 1/sqrt(32)

    if ((lane & 7) == 0) atomicAdd(&g_segsum[dst * 4 + (lane >> 3)], ex);

    uint2 vp = reinterpret_cast<const uint2*>(g_vb)[src * 32 + lane];
    float2 va = __bfloat1622float2(*reinterpret_cast<__nv_bfloat162*>(&vp.x));
    float2 vc = __bfloat1622float2(*reinterpret_cast<__nv_bfloat162*>(&vp.y));
    float* pd = &g_agg[dst * D + (size_t)lane * 4];
    asm volatile("red.global.add.v4.f32 [%0], {%1, %2, %3, %4};"
                 :: "l"(pd), "f"(va.x * ex), "f"(va.y * ex),
                    "f"(vc.x * ex), "f"(vc.y * ex)
                 : "memory");
}

// ---------------- fast GELU (tanh form via expf) -----------------------------
__device__ __forceinline__ float gelu_tanh(float x) {
    float u = 0.7978845608028654f * (x + 0.044715f * x * x * x);
    float e = __expf(2.f * u);
    return x * e / (e + 1.f);
}

// ---------------- tf32 conversion -------------------------------------------
__device__ __forceinline__ uint32_t f2tf32(float f) {
    uint32_t r;
    asm("cvt.rna.tf32.f32 %0, %1;" : "=r"(r) : "f"(f));
    return r;
}

// ---------------- A-row loader (fp32 or bf16 storage) ------------------------
template <bool BF16IN>
__device__ __forceinline__ float4 load4(const void* A, size_t elem_idx) {
    if (BF16IN) {
        uint2 t = *reinterpret_cast<const uint2*>(
            reinterpret_cast<const uint32_t*>(A) + (elem_idx >> 1));
        float2 a = __bfloat1622float2(*reinterpret_cast<__nv_bfloat162*>(&t.x));
        float2 b = __bfloat1622float2(*reinterpret_cast<__nv_bfloat162*>(&t.y));
        return make_float4(a.x, a.y, b.x, b.y);
    } else {
        return *reinterpret_cast<const float4*>(
            reinterpret_cast<const float*>(A) + elem_idx);
    }
}

#define ASTRIDE 20
#define BSTRIDE 132

// ---------------- generic tf32 GEMM body ------------------------------------
// EPI: 0=none, 1=gelu, 2=+residual.  BF16OUT: pack C to bf16x2.  BF16IN: A bf16.
template <int EPI, bool BF16OUT, bool BF16IN>
__device__ __forceinline__
void gemm_body(const void* __restrict__ A, const float* __restrict__ B,
               const float* __restrict__ bias, const float* __restrict__ res,
               float* __restrict__ C, int M, int N, int K) {
    __shared__ float As[2][128 * ASTRIDE];
    __shared__ float Bs[2][16 * BSTRIDE];

    const int tid  = threadIdx.x;
    const int lane = tid & 31;
    const int wid  = tid >> 5;
    const int bm   = blockIdx.x * 128;
    const int bn   = blockIdx.y * 128;
    const int wm   = (wid & 3) * 32;
    const int wn   = (wid >> 2) * 64;

    const int a_row  = tid >> 2;
    const int a_col  = (tid & 3) * 4;
    const int b_row  = tid >> 5;
    const int b_col  = (tid & 31) * 4;

    const int ar0 = min(bm + a_row,      M - 1);
    const int ar1 = min(bm + a_row + 64, M - 1);

    float acc[2][8][4];
    #pragma unroll
    for (int i = 0; i < 2; i++)
        #pragma unroll
        for (int j = 0; j < 8; j++)
            #pragma unroll
            for (int c = 0; c < 4; c++) acc[i][j][c] = 0.f;

    float4 a_reg0 = load4<BF16IN>(A, (size_t)ar0 * K + a_col);
    float4 a_reg1 = load4<BF16IN>(A, (size_t)ar1 * K + a_col);
    float4 b_reg0 = *reinterpret_cast<const float4*>(B + (size_t)b_row * N + bn + b_col);
    float4 b_reg1 = *reinterpret_cast<const float4*>(B + (size_t)(b_row + 8) * N + bn + b_col);

    const int nIter = K >> 4;
    for (int it = 0; it < nIter; it++) {
        const int cur = it & 1;
        float* pa0 = &As[cur][a_row * ASTRIDE + a_col];
        pa0[0] = __uint_as_float(f2tf32(a_reg0.x));
        pa0[1] = __uint_as_float(f2tf32(a_reg0.y));
        pa0[2] = __uint_as_float(f2tf32(a_reg0.z));
        pa0[3] = __uint_as_float(f2tf32(a_reg0.w));
        float* pa1 = &As[cur][(a_row + 64) * ASTRIDE + a_col];
        pa1[0] = __uint_as_float(f2tf32(a_reg1.x));
        pa1[1] = __uint_as_float(f2tf32(a_reg1.y));
        pa1[2] = __uint_as_float(f2tf32(a_reg1.z));
        pa1[3] = __uint_as_float(f2tf32(a_reg1.w));
        float* pb0 = &Bs[cur][b_row * BSTRIDE + b_col];
        pb0[0] = __uint_as_float(f2tf32(b_reg0.x));
        pb0[1] = __uint_as_float(f2tf32(b_reg0.y));
        pb0[2] = __uint_as_float(f2tf32(b_reg0.z));
        pb0[3] = __uint_as_float(f2tf32(b_reg0.w));
        float* pb1 = &Bs[cur][(b_row + 8) * BSTRIDE + b_col];
        pb1[0] = __uint_as_float(f2tf32(b_reg1.x));
        pb1[1] = __uint_as_float(f2tf32(b_reg1.y));
        pb1[2] = __uint_as_float(f2tf32(b_reg1.z));
        pb1[3] = __uint_as_float(f2tf32(b_reg1.w));
        __syncthreads();

        if (it + 1 < nIter) {
            int kn = (it + 1) << 4;
            a_reg0 = load4<BF16IN>(A, (size_t)ar0 * K + kn + a_col);
            a_reg1 = load4<BF16IN>(A, (size_t)ar1 * K + kn + a_col);
            b_reg0 = *reinterpret_cast<const float4*>(B + (size_t)(kn + b_row) * N + bn + b_col);
            b_reg1 = *reinterpret_cast<const float4*>(B + (size_t)(kn + b_row + 8) * N + bn + b_col);
        }

        #pragma unroll
        for (int ks = 0; ks < 16; ks += 8) {
            uint32_t af[2][4];
            #pragma unroll
            for (int i = 0; i < 2; i++) {
                int m = wm + i * 16 + (lane >> 2);
                int c = ks + (lane & 3);
                af[i][0] = __float_as_uint(As[cur][m * ASTRIDE + c]);
                af[i][1] = __float_as_uint(As[cur][(m + 8) * ASTRIDE + c]);
                af[i][2] = __float_as_uint(As[cur][m * ASTRIDE + c + 4]);
                af[i][3] = __float_as_uint(As[cur][(m + 8) * ASTRIDE + c + 4]);
            }
            uint32_t bf[8][2];
            #pragma unroll
            for (int j = 0; j < 8; j++) {
                int n = wn + j * 8 + (lane >> 2);
                int r = ks + (lane & 3);
                bf[j][0] = __float_as_uint(Bs[cur][r * BSTRIDE + n]);
                bf[j][1] = __float_as_uint(Bs[cur][(r + 4) * BSTRIDE + n]);
            }
            #pragma unroll
            for (int i = 0; i < 2; i++)
                #pragma unroll
                for (int j = 0; j < 8; j++) {
                    asm volatile(
                        "mma.sync.aligned.m16n8k8.row.col.f32.tf32.tf32.f32 "
                        "{%0,%1,%2,%3}, {%4,%5,%6,%7}, {%8,%9}, {%0,%1,%2,%3};"
                        : "+f"(acc[i][j][0]), "+f"(acc[i][j][1]),
                          "+f"(acc[i][j][2]), "+f"(acc[i][j][3])
                        : "r"(af[i][0]), "r"(af[i][1]), "r"(af[i][2]), "r"(af[i][3]),
                          "r"(bf[j][0]), "r"(bf[j][1]));
                }
        }
    }

    uint32_t* Cb = reinterpret_cast<uint32_t*>(C);
    #pragma unroll
    for (int i = 0; i < 2; i++) {
        int r0 = bm + wm + i * 16 + (lane >> 2);
        int r1 = r0 + 8;
        #pragma unroll
        for (int j = 0; j < 8; j++) {
            int c = bn + wn + j * 8 + (lane & 3) * 2;
            float b0 = bias[c], b1 = bias[c + 1];
            float v00 = acc[i][j][0] + b0, v01 = acc[i][j][1] + b1;
            float v10 = acc[i][j][2] + b0, v11 = acc[i][j][3] + b1;
            if (EPI == 1) {
                v00 = gelu_tanh(v00); v01 = gelu_tanh(v01);
                v10 = gelu_tanh(v10); v11 = gelu_tanh(v11);
            }
            if (r0 < M) {
                if (EPI == 2) {
                    float2 rv = *reinterpret_cast<const float2*>(res + (size_t)r0 * N + c);
                    v00 += rv.x; v01 += rv.y;
                }
                if (BF16OUT) {
                    __nv_bfloat162 h = __float22bfloat162_rn(make_float2(v00, v01));
                    Cb[(size_t)r0 * (N >> 1) + (c >> 1)] = *reinterpret_cast<uint32_t*>(&h);
                } else {
                    *reinterpret_cast<float2*>(C + (size_t)r0 * N + c) = make_float2(v00, v01);
                }
            }
            if (r1 < M) {
                if (EPI == 2) {
                    float2 rv = *reinterpret_cast<const float2*>(res + (size_t)r1 * N + c);
                    v10 += rv.x; v11 += rv.y;
                }
                if (BF16OUT) {
                    __nv_bfloat162 h = __float22bfloat162_rn(make_float2(v10, v11));
                    Cb[(size_t)r1 * (N >> 1) + (c >> 1)] = *reinterpret_cast<uint32_t*>(&h);
                } else {
                    *reinterpret_cast<float2*>(C + (size_t)r1 * N + c) = make_float2(v10, v11);
                }
            }
        }
    }
}

template <int EPI, bool BF16OUT, bool BF16IN>
__global__ __launch_bounds__(256, 2)
void mma_gemm_kernel(const void* __restrict__ A, const float* __restrict__ B,
                     const float* __restrict__ bias, const float* __restrict__ res,
                     float* __restrict__ C, int M, int N, int K) {
    gemm_body<EPI, BF16OUT, BF16IN>(A, B, bias, res, C, M, N, K);
}

// fused Q/K/V projection: all outputs bf16 (q/k/v consumed only by edge pass)
__global__ __launch_bounds__(256, 2)
void mma_gemm_qkv_kernel(const float* __restrict__ A,
                         const float* __restrict__ Wq, const float* __restrict__ Wk,
                         const float* __restrict__ Wv,
                         const float* __restrict__ bq, const float* __restrict__ bk,
                         const float* __restrict__ bv, int M) {
    int z = blockIdx.z;
    const float* B  = (z == 0) ? Wq : (z == 1) ? Wk : Wv;
    const float* bi = (z == 0) ? bq : (z == 1) ? bk : bv;
    float* C = reinterpret_cast<float*>((z == 0) ? g_qb : (z == 1) ? g_kb : g_vb);
    gemm_body<0, true, false>(A, B, bi, nullptr, C, M, D, D);
}

// ---------------- fused Wo GEMM: A-normalize + residual + LayerNorm ---------
// C_ln = LayerNorm( (agg/segsum) @ Wo + bo + x ) ; K = N = 128 fixed.
__global__ __launch_bounds__(256, 2)
void mma_gemm_wo_ln_kernel(const float* __restrict__ A,   // g_agg (unnormalized)
                           const float* __restrict__ Bw,
                           const float* __restrict__ bias,
                           const float* __restrict__ x,
                           const float* __restrict__ lng,
                           const float* __restrict__ lnb,
                           float* __restrict__ C, int M) {
    __shared__ float As[2][128 * ASTRIDE];
    __shared__ float Bs[2][16 * BSTRIDE];
    __shared__ float row_s[128];
    __shared__ float row_sq[128];

    const int tid  = threadIdx.x;
    const int lane = tid & 31;
    const int wid  = tid >> 5;
    const int bm   = blockIdx.x * 128;
    const int wm   = (wid & 3) * 32;
    const int wn   = (wid >> 2) * 64;

    const int a_row  = tid >> 2;
    const int a_col  = (tid & 3) * 4;
    const int b_row  = tid >> 5;
    const int b_col  = (tid & 31) * 4;

    const int ar0 = min(bm + a_row,      M - 1);
    const int ar1 = min(bm + a_row + 64, M - 1);

    if (tid < 128) { row_s[tid] = 0.f; row_sq[tid] = 0.f; }

    // per-row softmax-denominator reciprocals (4 heads)
    float4 ss0 = *reinterpret_cast<const float4*>(g_segsum + (size_t)ar0 * 4);
    float4 ss1 = *reinterpret_cast<const float4*>(g_segsum + (size_t)ar1 * 4);
    float rcp0[4], rcp1[4];
    rcp0[0] = ss0.x > 0.f ? __frcp_rn(ss0.x) : 0.f;
    rcp0[1] = ss0.y > 0.f ? __frcp_rn(ss0.y) : 0.f;
    rcp0[2] = ss0.z > 0.f ? __frcp_rn(ss0.z) : 0.f;
    rcp0[3] = ss0.w > 0.f ? __frcp_rn(ss0.w) : 0.f;
    rcp1[0] = ss1.x > 0.f ? __frcp_rn(ss1.x) : 0.f;
    rcp1[1] = ss1.y > 0.f ? __frcp_rn(ss1.y) : 0.f;
    rcp1[2] = ss1.z > 0.f ? __frcp_rn(ss1.z) : 0.f;
    rcp1[3] = ss1.w > 0.f ? __frcp_rn(ss1.w) : 0.f;

    float acc[2][8][4];
    #pragma unroll
    for (int i = 0; i < 2; i++)
        #pragma unroll
        for (int j = 0; j < 8; j++)
            #pragma unroll
            for (int c = 0; c < 4; c++) acc[i][j][c] = 0.f;

    float4 a_reg0 = *reinterpret_cast<const float4*>(A + (size_t)ar0 * D + a_col);
    float4 a_reg1 = *reinterpret_cast<const float4*>(A + (size_t)ar1 * D + a_col);
    float4 b_reg0 = *reinterpret_cast<const float4*>(Bw + (size_t)b_row * D + b_col);
    float4 b_reg1 = *reinterpret_cast<const float4*>(Bw + (size_t)(b_row + 8) * D + b_col);

    #pragma unroll
    for (int it = 0; it < 8; it++) {           // K = 128, kb = 16
        const int cur = it & 1;
        const int h = it >> 1;                  // head of this k-chunk
        float n0 = rcp0[h], n1 = rcp1[h];
        float* pa0 = &As[cur][a_row * ASTRIDE + a_col];
        pa0[0] = __uint_as_float(f2tf32(a_reg0.x * n0));
        pa0[1] = __uint_as_float(f2tf32(a_reg0.y * n0));
        pa0[2] = __uint_as_float(f2tf32(a_reg0.z * n0));
        pa0[3] = __uint_as_float(f2tf32(a_reg0.w * n0));
        float* pa1 = &As[cur][(a_row + 64) * ASTRIDE + a_col];
        pa1[0] = __uint_as_float(f2tf32(a_reg1.x * n1));
        pa1[1] = __uint_as_float(f2tf32(a_reg1.y * n1));
        pa1[2] = __uint_as_float(f2tf32(a_reg1.z * n1));
        pa1[3] = __uint_as_float(f2tf32(a_reg1.w * n1));
        float* pb0 = &Bs[cur][b_row * BSTRIDE + b_col];
        pb0[0] = __uint_as_float(f2tf32(b_reg0.x));
        pb0[1] = __uint_as_float(f2tf32(b_reg0.y));
        pb0[2] = __uint_as_float(f2tf32(b_reg0.z));
        pb0[3] = __uint_as_float(f2tf32(b_reg0.w));
        float* pb1 = &Bs[cur][(b_row + 8) * BSTRIDE + b_col];
        pb1[0] = __uint_as_float(f2tf32(b_reg1.x));
        pb1[1] = __uint_as_float(f2tf32(b_reg1.y));
        pb1[2] = __uint_as_float(f2tf32(b_reg1.z));
        pb1[3] = __uint_as_float(f2tf32(b_reg1.w));
        __syncthreads();

        if (it + 1 < 8) {
            int kn = (it + 1) << 4;
            a_reg0 = *reinterpret_cast<const float4*>(A + (size_t)ar0 * D + kn + a_col);
            a_reg1 = *reinterpret_cast<const float4*>(A + (size_t)ar1 * D + kn + a_col);
            b_reg0 = *reinterpret_cast<const float4*>(Bw + (size_t)(kn + b_row) * D + b_col);
            b_reg1 = *reinterpret_cast<const float4*>(Bw + (size_t)(kn + b_row + 8) * D + b_col);
        }

        #pragma unroll
        for (int ks = 0; ks < 16; ks += 8) {
            uint32_t af[2][4];
            #pragma unroll
            for (int i = 0; i < 2; i++) {
                int m = wm + i * 16 + (lane >> 2);
                int c = ks + (lane & 3);
                af[i][0] = __float_as_uint(As[cur][m * ASTRIDE + c]);
                af[i][1] = __float_as_uint(As[cur][(m + 8) * ASTRIDE + c]);
                af[i][2] = __float_as_uint(As[cur][m * ASTRIDE + c + 4]);
                af[i][3] = __float_as_uint(As[cur][(m + 8) * ASTRIDE + c + 4]);
            }
            uint32_t bf[8][2];
            #pragma unroll
            for (int j = 0; j < 8; j++) {
                int n = wn + j * 8 + (lane >> 2);
                int r = ks + (lane & 3);
                bf[j][0] = __float_as_uint(Bs[cur][r * BSTRIDE + n]);
                bf[j][1] = __float_as_uint(Bs[cur][(r + 4) * BSTRIDE + n]);
            }
            #pragma unroll
            for (int i = 0; i < 2; i++)
                #pragma unroll
                for (int j = 0; j < 8; j++) {
                    asm volatile(
                        "mma.sync.aligned.m16n8k8.row.col.f32.tf32.tf32.f32 "
                        "{%0,%1,%2,%3}, {%4,%5,%6,%7}, {%8,%9}, {%0,%1,%2,%3};"
                        : "+f"(acc[i][j][0]), "+f"(acc[i][j][1]),
                          "+f"(acc[i][j][2]), "+f"(acc[i][j][3])
                        : "r"(af[i][0]), "r"(af[i][1]), "r"(af[i][2]), "r"(af[i][3]),
                          "r"(bf[j][0]), "r"(bf[j][1]));
                }
        }
    }

    // epilogue: bias + residual, per-row LN stats via smem atomics
    #pragma unroll
    for (int i = 0; i < 2; i++) {
        int lr0 = wm + i * 16 + (lane >> 2);
        int lr1 = lr0 + 8;
        int r0 = bm + lr0, r1 = bm + lr1;
        float s0 = 0.f, q0 = 0.f, s1 = 0.f, q1 = 0.f;
        #pragma unroll
        for (int j = 0; j < 8; j++) {
            int c = wn + j * 8 + (lane & 3) * 2;
            float b0 = bias[c], b1 = bias[c + 1];
            if (r0 < M) {
                float2 rv = *reinterpret_cast<const float2*>(x + (size_t)r0 * D + c);
                acc[i][j][0] += b0 + rv.x;
                acc[i][j][1] += b1 + rv.y;
                s0 += acc[i][j][0] + acc[i][j][1];
                q0 += acc[i][j][0] * acc[i][j][0] + acc[i][j][1] * acc[i][j][1];
            }
            if (r1 < M) {
                float2 rv = *reinterpret_cast<const float2*>(x + (size_t)r1 * D + c);
                acc[i][j][2] += b0 + rv.x;
                acc[i][j][3] += b1 + rv.y;
                s1 += acc[i][j][2] + acc[i][j][3];
                q1 += acc[i][j][2] * acc[i][j][2] + acc[i][j][3] * acc[i][j][3];
            }
        }
        if (r0 < M) { atomicAdd(&row_s[lr0], s0); atomicAdd(&row_sq[lr0], q0); }
        if (r1 < M) { atomicAdd(&row_s[lr1], s1); atomicAdd(&row_sq[lr1], q1); }
    }
    __syncthreads();
    if (tid < 128) {
        float mu  = row_s[tid] * (1.f / 128.f);
        float var = row_sq[tid] * (1.f / 128.f) - mu * mu;
        row_s[tid]  = mu;
        row_sq[tid] = rsqrtf(var + 1e-5f);
    }
    __syncthreads();

    #pragma unroll
    for (int i = 0; i < 2; i++) {
        int lr0 = wm + i * 16 + (lane >> 2);
        int lr1 = lr0 + 8;
        int r0 = bm + lr0, r1 = bm + lr1;
        float mu0 = row_s[lr0], rs0 = row_sq[lr0];
        float mu1 = row_s[lr1], rs1 = row_sq[lr1];
        #pragma unroll
        for (int j = 0; j < 8; j++) {
            int c = wn + j * 8 + (lane & 3) * 2;
            float g0 = lng[c], g1 = lng[c + 1];
            float bb0 = lnb[c], bb1 = lnb[c + 1];
            if (r0 < M) {
                float v0 = (acc[i][j][0] - mu0) * rs0 * g0 + bb0;
                float v1 = (acc[i][j][1] - mu0) * rs0 * g1 + bb1;
                *reinterpret_cast<float2*>(C + (size_t)r0 * D + c) = make_float2(v0, v1);
            }
            if (r1 < M) {
                float v0 = (acc[i][j][2] - mu1) * rs1 * g0 + bb0;
                float v1 = (acc[i][j][3] - mu1) * rs1 * g1 + bb1;
                *reinterpret_cast<float2*>(C + (size_t)r1 * D + c) = make_float2(v0, v1);
            }
        }
    }
}

// ---------------- launch ----------------------------------------------------
extern "C" void kernel_launch(void* const* d_in, const int* in_sizes, int n_in,
                              void* d_out, int out_size) {
    const float* x   = (const float*)d_in[0];
    const int*   ei  = (const int*)d_in[1];   // int32 (JAX x64 disabled)
    const float* Wq  = (const float*)d_in[2];
    const float* bq  = (const float*)d_in[3];
    const float* Wk  = (const float*)d_in[4];
    const float* bk  = (const float*)d_in[5];
    const float* Wv  = (const float*)d_in[6];
    const float* bv  = (const float*)d_in[7];
    const float* Wo  = (const float*)d_in[8];
    const float* bo  = (const float*)d_in[9];
    const float* lng = (const float*)d_in[10];
    const float* lnb = (const float*)d_in[11];
    const float* W1  = (const float*)d_in[12];
    const float* b1  = (const float*)d_in[13];
    const float* W2  = (const float*)d_in[14];
    const float* b2  = (const float*)d_in[15];

    int N = in_sizes[0] / D;   // 40000
    int E = in_sizes[1] / 2;   // 640000

    void *pagg, *pln, *phid;
    cudaGetSymbolAddress(&pagg, g_agg);
    cudaGetSymbolAddress(&pln,  g_ln);
    cudaGetSymbolAddress(&phid, g_hidden);

    float* agg = (float*)pagg;
    float* ln  = (float*)pln;

    int mb = (N + 127) / 128;          // 313 row blocks

    // 1. init accumulators (vectorized)
    init_kernel<<<(N * 32 + 255) / 256, 256>>>(N);

    // 2. fused q/k/v projections (all outputs bf16)
    dim3 gQKV(mb, 1, 3);
    mma_gemm_qkv_kernel<<<gQKV, 256>>>(x, Wq, Wk, Wv, bq, bk, bv, N);

    // 3. fused edge phase (bf16 gathers; no seg-max needed)
    int eblocks = (E * 32 + 255) / 256;
    edge_fused_kernel<<<eblocks, 256>>>(ei, E);

    // 4. fused: normalize + Wo projection + residual + LayerNorm -> g_ln
    mma_gemm_wo_ln_kernel<<<mb, 256>>>(agg, Wo, bo, x, lng, lnb, ln, N);

    // 5. MLP: gelu(ln @ W1 + b1) -> hidden (bf16), then @ W2 + b2 + ln -> d_out
    dim3 gH(mb, HID / 128);
    dim3 gD(mb, 1);
    mma_gemm_kernel<1, true,  false><<<gH, 256>>>(ln, W1, b1, nullptr,
                                                  (float*)phid, N, HID, D);
    mma_gemm_kernel<2, false, true><<<gD, 256>>>(phid, W2, b2, ln,
                                                 (float*)d_out, N, D, HID);
}

// round 8
// speedup vs baseline: 1.1836x; 1.1246x over previous
#include <cuda_runtime.h>
#include <cuda_bf16.h>
#include <math.h>
#include <stdint.h>

// Problem shape constants (fixed by the dataset)
#define NMAX 40000
#define EMAX 640000
#define D    128
#define HID  512

// ---------------- scratch (static device allocations; no cudaMalloc) --------
__device__ uint32_t g_qb[NMAX * (D / 2)];   // q in bf16x2
__device__ uint32_t g_kb[NMAX * (D / 2)];   // k in bf16x2
__device__ uint32_t g_vb[NMAX * (D / 2)];   // v in bf16x2
__device__ float    g_segsum[NMAX * 4];
__device__ float    g_agg[NMAX * D];
__device__ float    g_ln[NMAX * D];
__device__ uint32_t g_hidden[NMAX * (HID / 2)];  // hidden in bf16x2

// ---------------- init: zero accumulators (vectorized) ----------------------
__global__ void init_kernel(int n) {
    int i = blockIdx.x * blockDim.x + threadIdx.x;
    if (i < n * (D / 4)) reinterpret_cast<float4*>(g_agg)[i] =
        make_float4(0.f, 0.f, 0.f, 0.f);
    if (i < n) reinterpret_cast<float4*>(g_segsum)[i] =
        make_float4(0.f, 0.f, 0.f, 0.f);
}

// ---------------- fused edge pass (bf16 gathers) -----------------------------
// Scores have std ~0.05 -> softmax without max-subtract is safe (shift-inv).
__global__ void edge_fused_kernel(const int* __restrict__ ei, int E) {
    int e    = (blockIdx.x * blockDim.x + threadIdx.x) >> 5;
    int lane = threadIdx.x & 31;
    if (e >= E) return;
    size_t src = (size_t)ei[e];
    size_t dst = (size_t)ei[(size_t)E + e];

    uint2 qp = reinterpret_cast<const uint2*>(g_qb)[dst * 32 + lane];
    uint2 kp = reinterpret_cast<const uint2*>(g_kb)[src * 32 + lane];
    float2 qa = __bfloat1622float2(*reinterpret_cast<__nv_bfloat162*>(&qp.x));
    float2 qc = __bfloat1622float2(*reinterpret_cast<__nv_bfloat162*>(&qp.y));
    float2 ka = __bfloat1622float2(*reinterpret_cast<__nv_bfloat162*>(&kp.x));
    float2 kc = __bfloat1622float2(*reinterpret_cast<__nv_bfloat162*>(&kp.y));
    float p = qa.x * ka.x + qa.y * ka.y + qc.x * kc.x + qc.y * kc.y;
    p += __shfl_xor_sync(0xffffffffu, p, 4);
    p += __shfl_xor_sync(0xffffffffu, p, 2);
    p += __shfl_xor_sync(0xffffffffu, p, 1);
    float ex = __expf(p * 0.17677669529663687f);  // 1/sqrt(32)

    if ((lane & 7) == 0) atomicAdd(&g_segsum[dst * 4 + (lane >> 3)], ex);

    uint2 vp = reinterpret_cast<const uint2*>(g_vb)[src * 32 + lane];
    float2 va = __bfloat1622float2(*reinterpret_cast<__nv_bfloat162*>(&vp.x));
    float2 vc = __bfloat1622float2(*reinterpret_cast<__nv_bfloat162*>(&vp.y));
    float* pd = &g_agg[dst * D + (size_t)lane * 4];
    asm volatile("red.global.add.v4.f32 [%0], {%1, %2, %3, %4};"
                 :: "l"(pd), "f"(va.x * ex), "f"(va.y * ex),
                    "f"(vc.x * ex), "f"(vc.y * ex)
                 : "memory");
}

// ---------------- fast GELU (tanh form via expf) -----------------------------
__device__ __forceinline__ float gelu_tanh(float x) {
    float u = 0.7978845608028654f * (x + 0.044715f * x * x * x);
    float e = __expf(2.f * u);
    return x * e / (e + 1.f);
}

// ---------------- bf16 pack --------------------------------------------------
__device__ __forceinline__ uint32_t packbf(float x, float y) {
    __nv_bfloat162 h = __float22bfloat162_rn(make_float2(x, y));
    return *reinterpret_cast<uint32_t*>(&h);
}

// ---------------- A-row loader (fp32 or bf16 storage) ------------------------
template <bool BF16IN>
__device__ __forceinline__ float4 load4(const void* A, size_t elem_idx) {
    if (BF16IN) {
        uint2 t = *reinterpret_cast<const uint2*>(
            reinterpret_cast<const uint32_t*>(A) + (elem_idx >> 1));
        float2 a = __bfloat1622float2(*reinterpret_cast<__nv_bfloat162*>(&t.x));
        float2 b = __bfloat1622float2(*reinterpret_cast<__nv_bfloat162*>(&t.y));
        return make_float4(a.x, a.y, b.x, b.y);
    } else {
        return *reinterpret_cast<const float4*>(
            reinterpret_cast<const float*>(A) + elem_idx);
    }
}

#define AP 12   // u32 pitch per row (8 bf16x2 pairs + pad; bank-conflict-free)

// ---------------- bf16 m16n8k16 GEMM body ------------------------------------
// EPI: 0=none, 1=gelu, 2=+residual.  BF16OUT: pack C to bf16x2.  BF16IN: A bf16.
// NORM != 0: scale A rows by per-head reciprocal segsum (Wo path).
template <int EPI, bool BF16OUT, bool BF16IN, bool NORM>
__device__ __forceinline__
void gemm_body(const void* __restrict__ A, const float* __restrict__ B,
               const float* __restrict__ bias, const float* __restrict__ res,
               float* __restrict__ C, int M, int N, int K,
               const float* __restrict__ lng, const float* __restrict__ lnb) {
    __shared__ uint32_t As[2][128 * AP];   // bf16x2 pairs along k
    __shared__ uint32_t Bs[2][128 * AP];   // transposed: [n][kpair]
    __shared__ float row_s[128];
    __shared__ float row_sq[128];

    const int tid  = threadIdx.x;
    const int lane = tid & 31;
    const int wid  = tid >> 5;
    const int bm   = blockIdx.x * 128;
    const int bn   = blockIdx.y * 128;
    const int wm   = (wid & 3) * 32;
    const int wn   = (wid >> 2) * 64;

    // A global mapping: 2 rows x float4 per thread
    const int a_row = tid >> 2;
    const int a_col = (tid & 3) * 4;
    // B global mapping: n column + k half
    const int b_n     = tid & 127;
    const int b_khalf = tid >> 7;          // 0 or 1 -> k offsets 0-7 / 8-15

    const int ar0 = min(bm + a_row,      M - 1);
    const int ar1 = min(bm + a_row + 64, M - 1);

    if (NORM && tid < 128) { row_s[tid] = 0.f; row_sq[tid] = 0.f; }

    // per-row softmax-denominator reciprocals (Wo path only)
    float rcp0[4], rcp1[4];
    if (NORM) {
        float4 ss0 = *reinterpret_cast<const float4*>(g_segsum + (size_t)ar0 * 4);
        float4 ss1 = *reinterpret_cast<const float4*>(g_segsum + (size_t)ar1 * 4);
        rcp0[0] = ss0.x > 0.f ? __frcp_rn(ss0.x) : 0.f;
        rcp0[1] = ss0.y > 0.f ? __frcp_rn(ss0.y) : 0.f;
        rcp0[2] = ss0.z > 0.f ? __frcp_rn(ss0.z) : 0.f;
        rcp0[3] = ss0.w > 0.f ? __frcp_rn(ss0.w) : 0.f;
        rcp1[0] = ss1.x > 0.f ? __frcp_rn(ss1.x) : 0.f;
        rcp1[1] = ss1.y > 0.f ? __frcp_rn(ss1.y) : 0.f;
        rcp1[2] = ss1.z > 0.f ? __frcp_rn(ss1.z) : 0.f;
        rcp1[3] = ss1.w > 0.f ? __frcp_rn(ss1.w) : 0.f;
    }

    float acc[2][8][4];
    #pragma unroll
    for (int i = 0; i < 2; i++)
        #pragma unroll
        for (int j = 0; j < 8; j++)
            #pragma unroll
            for (int c = 0; c < 4; c++) acc[i][j][c] = 0.f;

    // prefetch first tile
    float4 a_reg0 = load4<BF16IN>(A, (size_t)ar0 * K + a_col);
    float4 a_reg1 = load4<BF16IN>(A, (size_t)ar1 * K + a_col);
    float b_reg[8];
    {
        const float* bp = B + (size_t)(b_khalf * 8) * N + bn + b_n;
        #pragma unroll
        for (int i = 0; i < 8; i++) b_reg[i] = bp[(size_t)i * N];
    }

    const int nIter = K >> 4;
    for (int it = 0; it < nIter; it++) {
        const int cur = it & 1;
        float n0 = 1.f, n1 = 1.f;
        if (NORM) { n0 = rcp0[it >> 1]; n1 = rcp1[it >> 1]; }
        // A -> smem (bf16 pairs)
        {
            uint2 pa = make_uint2(packbf(a_reg0.x * n0, a_reg0.y * n0),
                                  packbf(a_reg0.z * n0, a_reg0.w * n0));
            *reinterpret_cast<uint2*>(&As[cur][a_row * AP + (tid & 3) * 2]) = pa;
            uint2 pb = make_uint2(packbf(a_reg1.x * n1, a_reg1.y * n1),
                                  packbf(a_reg1.z * n1, a_reg1.w * n1));
            *reinterpret_cast<uint2*>(&As[cur][(a_row + 64) * AP + (tid & 3) * 2]) = pb;
        }
        // B -> smem transposed [n][kpair]
        {
            uint4 q = make_uint4(packbf(b_reg[0], b_reg[1]),
                                 packbf(b_reg[2], b_reg[3]),
                                 packbf(b_reg[4], b_reg[5]),
                                 packbf(b_reg[6], b_reg[7]));
            *reinterpret_cast<uint4*>(&Bs[cur][b_n * AP + b_khalf * 4]) = q;
        }
        __syncthreads();

        // prefetch next tile (overlaps with compute)
        if (it + 1 < nIter) {
            int kn = (it + 1) << 4;
            a_reg0 = load4<BF16IN>(A, (size_t)ar0 * K + kn + a_col);
            a_reg1 = load4<BF16IN>(A, (size_t)ar1 * K + kn + a_col);
            const float* bp = B + (size_t)(kn + b_khalf * 8) * N + bn + b_n;
            #pragma unroll
            for (int i = 0; i < 8; i++) b_reg[i] = bp[(size_t)i * N];
        }

        // fragments + 16 MMAs covering full k16
        uint32_t af[2][4];
        #pragma unroll
        for (int i = 0; i < 2; i++) {
            int m = wm + i * 16 + (lane >> 2);
            int c = lane & 3;
            af[i][0] = As[cur][m * AP + c];
            af[i][1] = As[cur][(m + 8) * AP + c];
            af[i][2] = As[cur][m * AP + c + 4];
            af[i][3] = As[cur][(m + 8) * AP + c + 4];
        }
        uint32_t bfr[8][2];
        #pragma unroll
        for (int j = 0; j < 8; j++) {
            int n = wn + j * 8 + (lane >> 2);
            int c = lane & 3;
            bfr[j][0] = Bs[cur][n * AP + c];
            bfr[j][1] = Bs[cur][n * AP + c + 4];
        }
        #pragma unroll
        for (int i = 0; i < 2; i++)
            #pragma unroll
            for (int j = 0; j < 8; j++) {
                asm volatile(
                    "mma.sync.aligned.m16n8k16.row.col.f32.bf16.bf16.f32 "
                    "{%0,%1,%2,%3}, {%4,%5,%6,%7}, {%8,%9}, {%0,%1,%2,%3};"
                    : "+f"(acc[i][j][0]), "+f"(acc[i][j][1]),
                      "+f"(acc[i][j][2]), "+f"(acc[i][j][3])
                    : "r"(af[i][0]), "r"(af[i][1]), "r"(af[i][2]), "r"(af[i][3]),
                      "r"(bfr[j][0]), "r"(bfr[j][1]));
            }
        __syncthreads();
    }

    if (!NORM) {
        uint32_t* Cb = reinterpret_cast<uint32_t*>(C);
        #pragma unroll
        for (int i = 0; i < 2; i++) {
            int r0 = bm + wm + i * 16 + (lane >> 2);
            int r1 = r0 + 8;
            #pragma unroll
            for (int j = 0; j < 8; j++) {
                int c = bn + wn + j * 8 + (lane & 3) * 2;
                float b0 = bias[c], b1 = bias[c + 1];
                float v00 = acc[i][j][0] + b0, v01 = acc[i][j][1] + b1;
                float v10 = acc[i][j][2] + b0, v11 = acc[i][j][3] + b1;
                if (EPI == 1) {
                    v00 = gelu_tanh(v00); v01 = gelu_tanh(v01);
                    v10 = gelu_tanh(v10); v11 = gelu_tanh(v11);
                }
                if (r0 < M) {
                    if (EPI == 2) {
                        float2 rv = *reinterpret_cast<const float2*>(res + (size_t)r0 * N + c);
                        v00 += rv.x; v01 += rv.y;
                    }
                    if (BF16OUT)
                        Cb[(size_t)r0 * (N >> 1) + (c >> 1)] = packbf(v00, v01);
                    else
                        *reinterpret_cast<float2*>(C + (size_t)r0 * N + c) = make_float2(v00, v01);
                }
                if (r1 < M) {
                    if (EPI == 2) {
                        float2 rv = *reinterpret_cast<const float2*>(res + (size_t)r1 * N + c);
                        v10 += rv.x; v11 += rv.y;
                    }
                    if (BF16OUT)
                        Cb[(size_t)r1 * (N >> 1) + (c >> 1)] = packbf(v10, v11);
                    else
                        *reinterpret_cast<float2*>(C + (size_t)r1 * N + c) = make_float2(v10, v11);
                }
            }
        }
    } else {
        // Wo path: bias + residual, per-row LayerNorm, write fp32
        #pragma unroll
        for (int i = 0; i < 2; i++) {
            int lr0 = wm + i * 16 + (lane >> 2);
            int lr1 = lr0 + 8;
            int r0 = bm + lr0, r1 = bm + lr1;
            float s0 = 0.f, q0 = 0.f, s1 = 0.f, q1 = 0.f;
            #pragma unroll
            for (int j = 0; j < 8; j++) {
                int c = wn + j * 8 + (lane & 3) * 2;
                float b0 = bias[c], b1 = bias[c + 1];
                if (r0 < M) {
                    float2 rv = *reinterpret_cast<const float2*>(res + (size_t)r0 * D + c);
                    acc[i][j][0] += b0 + rv.x;
                    acc[i][j][1] += b1 + rv.y;
                    s0 += acc[i][j][0] + acc[i][j][1];
                    q0 += acc[i][j][0] * acc[i][j][0] + acc[i][j][1] * acc[i][j][1];
                }
                if (r1 < M) {
                    float2 rv = *reinterpret_cast<const float2*>(res + (size_t)r1 * D + c);
                    acc[i][j][2] += b0 + rv.x;
                    acc[i][j][3] += b1 + rv.y;
                    s1 += acc[i][j][2] + acc[i][j][3];
                    q1 += acc[i][j][2] * acc[i][j][2] + acc[i][j][3] * acc[i][j][3];
                }
            }
            if (r0 < M) { atomicAdd(&row_s[lr0], s0); atomicAdd(&row_sq[lr0], q0); }
            if (r1 < M) { atomicAdd(&row_s[lr1], s1); atomicAdd(&row_sq[lr1], q1); }
        }
        __syncthreads();
        if (tid < 128) {
            float mu  = row_s[tid] * (1.f / 128.f);
            float var = row_sq[tid] * (1.f / 128.f) - mu * mu;
            row_s[tid]  = mu;
            row_sq[tid] = rsqrtf(var + 1e-5f);
        }
        __syncthreads();
        #pragma unroll
        for (int i = 0; i < 2; i++) {
            int lr0 = wm + i * 16 + (lane >> 2);
            int lr1 = lr0 + 8;
            int r0 = bm + lr0, r1 = bm + lr1;
            float mu0 = row_s[lr0], rs0 = row_sq[lr0];
            float mu1 = row_s[lr1], rs1 = row_sq[lr1];
            #pragma unroll
            for (int j = 0; j < 8; j++) {
                int c = wn + j * 8 + (lane & 3) * 2;
                float g0 = lng[c], g1 = lng[c + 1];
                float bb0 = lnb[c], bb1 = lnb[c + 1];
                if (r0 < M) {
                    float v0 = (acc[i][j][0] - mu0) * rs0 * g0 + bb0;
                    float v1 = (acc[i][j][1] - mu0) * rs0 * g1 + bb1;
                    *reinterpret_cast<float2*>(C + (size_t)r0 * D + c) = make_float2(v0, v1);
                }
                if (r1 < M) {
                    float v0 = (acc[i][j][2] - mu1) * rs1 * g0 + bb0;
                    float v1 = (acc[i][j][3] - mu1) * rs1 * g1 + bb1;
                    *reinterpret_cast<float2*>(C + (size_t)r1 * D + c) = make_float2(v0, v1);
                }
            }
        }
    }
}

template <int EPI, bool BF16OUT, bool BF16IN>
__global__ __launch_bounds__(256, 2)
void mma_gemm_kernel(const void* __restrict__ A, const float* __restrict__ B,
                     const float* __restrict__ bias, const float* __restrict__ res,
                     float* __restrict__ C, int M, int N, int K) {
    gemm_body<EPI, BF16OUT, BF16IN, false>(A, B, bias, res, C, M, N, K,
                                           nullptr, nullptr);
}

// fused Q/K/V projection: all outputs bf16
__global__ __launch_bounds__(256, 2)
void mma_gemm_qkv_kernel(const float* __restrict__ A,
                         const float* __restrict__ Wq, const float* __restrict__ Wk,
                         const float* __restrict__ Wv,
                         const float* __restrict__ bq, const float* __restrict__ bk,
                         const float* __restrict__ bv, int M) {
    int z = blockIdx.z;
    const float* B  = (z == 0) ? Wq : (z == 1) ? Wk : Wv;
    const float* bi = (z == 0) ? bq : (z == 1) ? bk : bv;
    float* C = reinterpret_cast<float*>((z == 0) ? g_qb : (z == 1) ? g_kb : g_vb);
    gemm_body<0, true, false, false>(A, B, bi, nullptr, C, M, D, D,
                                     nullptr, nullptr);
}

// Wo: normalize A by segsum + GEMM + residual + LayerNorm
__global__ __launch_bounds__(256, 2)
void mma_gemm_wo_ln_kernel(const float* __restrict__ A, const float* __restrict__ Bw,
                           const float* __restrict__ bias, const float* __restrict__ x,
                           const float* __restrict__ lng, const float* __restrict__ lnb,
                           float* __restrict__ C, int M) {
    gemm_body<2, false, false, true>(A, Bw, bias, x, C, M, D, D, lng, lnb);
}

// ---------------- launch ----------------------------------------------------
extern "C" void kernel_launch(void* const* d_in, const int* in_sizes, int n_in,
                              void* d_out, int out_size) {
    const float* x   = (const float*)d_in[0];
    const int*   ei  = (const int*)d_in[1];   // int32 (JAX x64 disabled)
    const float* Wq  = (const float*)d_in[2];
    const float* bq  = (const float*)d_in[3];
    const float* Wk  = (const float*)d_in[4];
    const float* bk  = (const float*)d_in[5];
    const float* Wv  = (const float*)d_in[6];
    const float* bv  = (const float*)d_in[7];
    const float* Wo  = (const float*)d_in[8];
    const float* bo  = (const float*)d_in[9];
    const float* lng = (const float*)d_in[10];
    const float* lnb = (const float*)d_in[11];
    const float* W1  = (const float*)d_in[12];
    const float* b1  = (const float*)d_in[13];
    const float* W2  = (const float*)d_in[14];
    const float* b2  = (const float*)d_in[15];

    int N = in_sizes[0] / D;   // 40000
    int E = in_sizes[1] / 2;   // 640000

    void *pagg, *pln, *phid;
    cudaGetSymbolAddress(&pagg, g_agg);
    cudaGetSymbolAddress(&pln,  g_ln);
    cudaGetSymbolAddress(&phid, g_hidden);

    float* agg = (float*)pagg;
    float* ln  = (float*)pln;

    int mb = (N + 127) / 128;          // 313 row blocks

    // 1. init accumulators (vectorized)
    init_kernel<<<(N * 32 + 255) / 256, 256>>>(N);

    // 2. fused q/k/v projections (bf16 tensor cores, outputs bf16)
    dim3 gQKV(mb, 1, 3);
    mma_gemm_qkv_kernel<<<gQKV, 256>>>(x, Wq, Wk, Wv, bq, bk, bv, N);

    // 3. fused edge phase (bf16 gathers; no seg-max needed)
    int eblocks = (E * 32 + 255) / 256;
    edge_fused_kernel<<<eblocks, 256>>>(ei, E);

    // 4. fused: normalize + Wo projection + residual + LayerNorm -> g_ln
    mma_gemm_wo_ln_kernel<<<mb, 256>>>(agg, Wo, bo, x, lng, lnb, ln, N);

    // 5. MLP: gelu(ln @ W1 + b1) -> hidden (bf16), then @ W2 + b2 + ln -> d_out
    dim3 gH(mb, HID / 128);
    dim3 gD(mb, 1);
    mma_gemm_kernel<1, true,  false><<<gH, 256>>>(ln, W1, b1, nullptr,
                                                  (float*)phid, N, HID, D);
    mma_gemm_kernel<2, false, true><<<gD, 256>>>(phid, W2, b2, ln,
                                                 (float*)d_out, N, D, HID);
}

// round 9
// speedup vs baseline: 1.2564x; 1.0615x over previous
#include <cuda_runtime.h>
#include <cuda_bf16.h>
#include <math.h>
#include <stdint.h>

#define NMAX 40000
#define EMAX 640000
#define D    128
#define HID  512

// ---------------- scratch ----------------------------------------------------
__device__ uint32_t g_qb[NMAX * (D / 2)];
__device__ uint32_t g_kb[NMAX * (D / 2)];
__device__ uint32_t g_vb[NMAX * (D / 2)];
__device__ float    g_segsum[NMAX * 4];
__device__ float    g_agg[NMAX * D];
__device__ float    g_ln[NMAX * D];
__device__ uint32_t g_lnb[NMAX * (D / 2)];       // ln in bf16x2
__device__ uint32_t g_hidden[NMAX * (HID / 2)];  // hidden in bf16x2
__device__ uint32_t g_wts[98304];                // all weights bf16, transposed [n][k]

// weight segment offsets (u32 units) inside g_wts
#define WQ_OFF 0
#define WK_OFF 8192
#define WV_OFF 16384
#define WO_OFF 24576
#define W1_OFF 32768
#define W2_OFF 65536

// ---------------- init -------------------------------------------------------
__global__ void init_kernel(int n) {
    int i = blockIdx.x * blockDim.x + threadIdx.x;
    if (i < n * (D / 4)) reinterpret_cast<float4*>(g_agg)[i] =
        make_float4(0.f, 0.f, 0.f, 0.f);
    if (i < n) reinterpret_cast<float4*>(g_segsum)[i] =
        make_float4(0.f, 0.f, 0.f, 0.f);
}

__device__ __forceinline__ uint32_t packbf(float x, float y) {
    __nv_bfloat162 h = __float22bfloat162_rn(make_float2(x, y));
    return *reinterpret_cast<uint32_t*>(&h);
}

// ---------------- weight convert + transpose: W[K,N] fp32 -> Wt[n][k] bf16 ---
__global__ void wconv_kernel(const float* __restrict__ Wq, const float* __restrict__ Wk,
                             const float* __restrict__ Wv, const float* __restrict__ Wo,
                             const float* __restrict__ W1, const float* __restrict__ W2) {
    int i = blockIdx.x * blockDim.x + threadIdx.x;   // u32 output index
    if (i >= 98304) return;
    const float* src; int off, Nn, Kk;
    if      (i < WK_OFF) { src = Wq; off = WQ_OFF; Nn = 128; Kk = 128; }
    else if (i < WV_OFF) { src = Wk; off = WK_OFF; Nn = 128; Kk = 128; }
    else if (i < WO_OFF) { src = Wv; off = WV_OFF; Nn = 128; Kk = 128; }
    else if (i < W1_OFF) { src = Wo; off = WO_OFF; Nn = 128; Kk = 128; }
    else if (i < W2_OFF) { src = W1; off = W1_OFF; Nn = 512; Kk = 128; }
    else                 { src = W2; off = W2_OFF; Nn = 128; Kk = 512; }
    int idx = i - off;
    int kh  = Kk >> 1;
    int n   = idx / kh;
    int kp  = idx % kh;
    float v0 = src[(size_t)(2 * kp)     * Nn + n];
    float v1 = src[(size_t)(2 * kp + 1) * Nn + n];
    g_wts[i] = packbf(v0, v1);
}

// ---------------- fused edge pass (bf16 gathers) -----------------------------
__global__ void edge_fused_kernel(const int* __restrict__ ei, int E) {
    int e    = (blockIdx.x * blockDim.x + threadIdx.x) >> 5;
    int lane = threadIdx.x & 31;
    if (e >= E) return;
    size_t src = (size_t)ei[e];
    size_t dst = (size_t)ei[(size_t)E + e];

    uint2 qp = reinterpret_cast<const uint2*>(g_qb)[dst * 32 + lane];
    uint2 kp = reinterpret_cast<const uint2*>(g_kb)[src * 32 + lane];
    float2 qa = __bfloat1622float2(*reinterpret_cast<__nv_bfloat162*>(&qp.x));
    float2 qc = __bfloat1622float2(*reinterpret_cast<__nv_bfloat162*>(&qp.y));
    float2 ka = __bfloat1622float2(*reinterpret_cast<__nv_bfloat162*>(&kp.x));
    float2 kc = __bfloat1622float2(*reinterpret_cast<__nv_bfloat162*>(&kp.y));
    float p = qa.x * ka.x + qa.y * ka.y + qc.x * kc.x + qc.y * kc.y;
    p += __shfl_xor_sync(0xffffffffu, p, 4);
    p += __shfl_xor_sync(0xffffffffu, p, 2);
    p += __shfl_xor_sync(0xffffffffu, p, 1);
    float ex = __expf(p * 0.17677669529663687f);

    if ((lane & 7) == 0) atomicAdd(&g_segsum[dst * 4 + (lane >> 3)], ex);

    uint2 vp = reinterpret_cast<const uint2*>(g_vb)[src * 32 + lane];
    float2 va = __bfloat1622float2(*reinterpret_cast<__nv_bfloat162*>(&vp.x));
    float2 vc = __bfloat1622float2(*reinterpret_cast<__nv_bfloat162*>(&vp.y));
    float* pd = &g_agg[dst * D + (size_t)lane * 4];
    asm volatile("red.global.add.v4.f32 [%0], {%1, %2, %3, %4};"
                 :: "l"(pd), "f"(va.x * ex), "f"(va.y * ex),
                    "f"(vc.x * ex), "f"(vc.y * ex)
                 : "memory");
}

__device__ __forceinline__ float gelu_tanh(float x) {
    float u = 0.7978845608028654f * (x + 0.044715f * x * x * x);
    float e = __expf(2.f * u);
    return x * e / (e + 1.f);
}

#define AP 12   // u32 pitch per smem row

// ---------------- bf16 m16n8k16 GEMM body ------------------------------------
// B: pre-transposed bf16 [n][k] (u32 pairs).  A: fp32 (A_BF16=0) or bf16.
// EPI: 0=none, 1=gelu, 2=+residual.  NORM: per-head segsum normalize (Wo path).
template <int EPI, bool BF16OUT, bool A_BF16, bool NORM>
__device__ __forceinline__
void gemm_body(const void* __restrict__ A, const uint32_t* __restrict__ Bt,
               const float* __restrict__ bias, const float* __restrict__ res,
               float* __restrict__ C, int M, int N, int K,
               const float* __restrict__ lng, const float* __restrict__ lnb,
               uint32_t* __restrict__ Cb2) {
    __shared__ uint32_t As[2][128 * AP];
    __shared__ uint32_t Bs[2][128 * AP];
    __shared__ float row_s[128];
    __shared__ float row_sq[128];

    const int tid  = threadIdx.x;
    const int lane = tid & 31;
    const int wid  = tid >> 5;
    const int bm   = blockIdx.x * 128;
    const int bn   = blockIdx.y * 128;
    const int wm   = (wid & 3) * 32;
    const int wn   = (wid >> 2) * 64;
    const int khalf = tid & 1;
    const int kh    = K >> 1;     // u32 per bf16 row

    // B mapping: one row of Bt per 2 threads
    const int b_n = tid >> 1;

    float rcp0[4], rcp1[4];
    float4 a_reg0, a_reg1;
    uint4  a_regb;
    int ar0, ar1, arb;
    if (A_BF16) {
        arb = min(bm + (tid >> 1), M - 1);
    } else {
        ar0 = min(bm + (tid >> 2),      M - 1);
        ar1 = min(bm + (tid >> 2) + 64, M - 1);
    }
    const int a_col = (tid & 3) * 4;

    if (NORM) {
        if (tid < 128) { row_s[tid] = 0.f; row_sq[tid] = 0.f; }
        float4 ss0 = *reinterpret_cast<const float4*>(g_segsum + (size_t)ar0 * 4);
        float4 ss1 = *reinterpret_cast<const float4*>(g_segsum + (size_t)ar1 * 4);
        rcp0[0] = ss0.x > 0.f ? __frcp_rn(ss0.x) : 0.f;
        rcp0[1] = ss0.y > 0.f ? __frcp_rn(ss0.y) : 0.f;
        rcp0[2] = ss0.z > 0.f ? __frcp_rn(ss0.z) : 0.f;
        rcp0[3] = ss0.w > 0.f ? __frcp_rn(ss0.w) : 0.f;
        rcp1[0] = ss1.x > 0.f ? __frcp_rn(ss1.x) : 0.f;
        rcp1[1] = ss1.y > 0.f ? __frcp_rn(ss1.y) : 0.f;
        rcp1[2] = ss1.z > 0.f ? __frcp_rn(ss1.z) : 0.f;
        rcp1[3] = ss1.w > 0.f ? __frcp_rn(ss1.w) : 0.f;
    }

    float acc[2][8][4];
    #pragma unroll
    for (int i = 0; i < 2; i++)
        #pragma unroll
        for (int j = 0; j < 8; j++)
            #pragma unroll
            for (int c = 0; c < 4; c++) acc[i][j][c] = 0.f;

    // prefetch first tile
    if (A_BF16) {
        a_regb = *reinterpret_cast<const uint4*>(
            reinterpret_cast<const uint32_t*>(A) + (size_t)arb * (K >> 1) + khalf * 4);
    } else {
        a_reg0 = *reinterpret_cast<const float4*>(
            reinterpret_cast<const float*>(A) + (size_t)ar0 * K + a_col);
        a_reg1 = *reinterpret_cast<const float4*>(
            reinterpret_cast<const float*>(A) + (size_t)ar1 * K + a_col);
    }
    uint4 b_regb = *reinterpret_cast<const uint4*>(
        Bt + (size_t)(bn + b_n) * kh + khalf * 4);

    const int nIter = K >> 4;
    for (int it = 0; it < nIter; it++) {
        const int cur = it & 1;
        // stage A
        if (A_BF16) {
            *reinterpret_cast<uint4*>(&As[cur][(tid >> 1) * AP + khalf * 4]) = a_regb;
        } else {
            float n0 = 1.f, n1 = 1.f;
            if (NORM) { n0 = rcp0[it >> 1]; n1 = rcp1[it >> 1]; }
            uint2 pa = make_uint2(packbf(a_reg0.x * n0, a_reg0.y * n0),
                                  packbf(a_reg0.z * n0, a_reg0.w * n0));
            *reinterpret_cast<uint2*>(&As[cur][(tid >> 2) * AP + (tid & 3) * 2]) = pa;
            uint2 pb = make_uint2(packbf(a_reg1.x * n1, a_reg1.y * n1),
                                  packbf(a_reg1.z * n1, a_reg1.w * n1));
            *reinterpret_cast<uint2*>(&As[cur][((tid >> 2) + 64) * AP + (tid & 3) * 2]) = pb;
        }
        // stage B
        *reinterpret_cast<uint4*>(&Bs[cur][b_n * AP + khalf * 4]) = b_regb;
        __syncthreads();

        // prefetch next tile
        if (it + 1 < nIter) {
            int kn = (it + 1) << 4;
            if (A_BF16) {
                a_regb = *reinterpret_cast<const uint4*>(
                    reinterpret_cast<const uint32_t*>(A) +
                    (size_t)arb * (K >> 1) + (kn >> 1) + khalf * 4);
            } else {
                a_reg0 = *reinterpret_cast<const float4*>(
                    reinterpret_cast<const float*>(A) + (size_t)ar0 * K + kn + a_col);
                a_reg1 = *reinterpret_cast<const float4*>(
                    reinterpret_cast<const float*>(A) + (size_t)ar1 * K + kn + a_col);
            }
            b_regb = *reinterpret_cast<const uint4*>(
                Bt + (size_t)(bn + b_n) * kh + (kn >> 1) + khalf * 4);
        }

        // fragments + 16 MMAs (full k16)
        uint32_t af[2][4];
        #pragma unroll
        for (int i = 0; i < 2; i++) {
            int m = wm + i * 16 + (lane >> 2);
            int c = lane & 3;
            af[i][0] = As[cur][m * AP + c];
            af[i][1] = As[cur][(m + 8) * AP + c];
            af[i][2] = As[cur][m * AP + c + 4];
            af[i][3] = As[cur][(m + 8) * AP + c + 4];
        }
        uint32_t bfr[8][2];
        #pragma unroll
        for (int j = 0; j < 8; j++) {
            int n = wn + j * 8 + (lane >> 2);
            int c = lane & 3;
            bfr[j][0] = Bs[cur][n * AP + c];
            bfr[j][1] = Bs[cur][n * AP + c + 4];
        }
        #pragma unroll
        for (int i = 0; i < 2; i++)
            #pragma unroll
            for (int j = 0; j < 8; j++) {
                asm volatile(
                    "mma.sync.aligned.m16n8k16.row.col.f32.bf16.bf16.f32 "
                    "{%0,%1,%2,%3}, {%4,%5,%6,%7}, {%8,%9}, {%0,%1,%2,%3};"
                    : "+f"(acc[i][j][0]), "+f"(acc[i][j][1]),
                      "+f"(acc[i][j][2]), "+f"(acc[i][j][3])
                    : "r"(af[i][0]), "r"(af[i][1]), "r"(af[i][2]), "r"(af[i][3]),
                      "r"(bfr[j][0]), "r"(bfr[j][1]));
            }
        // single barrier per iter: next store targets the other buffer; the
        // following reuse of this buffer is ordered behind the next barrier.
        __syncthreads();
    }

    if (!NORM) {
        uint32_t* Cb = reinterpret_cast<uint32_t*>(C);
        #pragma unroll
        for (int i = 0; i < 2; i++) {
            int r0 = bm + wm + i * 16 + (lane >> 2);
            int r1 = r0 + 8;
            #pragma unroll
            for (int j = 0; j < 8; j++) {
                int c = bn + wn + j * 8 + (lane & 3) * 2;
                float b0 = bias[c], b1 = bias[c + 1];
                float v00 = acc[i][j][0] + b0, v01 = acc[i][j][1] + b1;
                float v10 = acc[i][j][2] + b0, v11 = acc[i][j][3] + b1;
                if (EPI == 1) {
                    v00 = gelu_tanh(v00); v01 = gelu_tanh(v01);
                    v10 = gelu_tanh(v10); v11 = gelu_tanh(v11);
                }
                if (r0 < M) {
                    if (EPI == 2) {
                        float2 rv = *reinterpret_cast<const float2*>(res + (size_t)r0 * N + c);
                        v00 += rv.x; v01 += rv.y;
                    }
                    if (BF16OUT)
                        Cb[(size_t)r0 * (N >> 1) + (c >> 1)] = packbf(v00, v01);
                    else
                        *reinterpret_cast<float2*>(C + (size_t)r0 * N + c) = make_float2(v00, v01);
                }
                if (r1 < M) {
                    if (EPI == 2) {
                        float2 rv = *reinterpret_cast<const float2*>(res + (size_t)r1 * N + c);
                        v10 += rv.x; v11 += rv.y;
                    }
                    if (BF16OUT)
                        Cb[(size_t)r1 * (N >> 1) + (c >> 1)] = packbf(v10, v11);
                    else
                        *reinterpret_cast<float2*>(C + (size_t)r1 * N + c) = make_float2(v10, v11);
                }
            }
        }
    } else {
        // Wo path: bias + residual -> LayerNorm -> fp32 C and bf16 Cb2
        #pragma unroll
        for (int i = 0; i < 2; i++) {
            int lr0 = wm + i * 16 + (lane >> 2);
            int lr1 = lr0 + 8;
            int r0 = bm + lr0, r1 = bm + lr1;
            float s0 = 0.f, q0 = 0.f, s1 = 0.f, q1 = 0.f;
            #pragma unroll
            for (int j = 0; j < 8; j++) {
                int c = wn + j * 8 + (lane & 3) * 2;
                float b0 = bias[c], b1 = bias[c + 1];
                if (r0 < M) {
                    float2 rv = *reinterpret_cast<const float2*>(res + (size_t)r0 * D + c);
                    acc[i][j][0] += b0 + rv.x;
                    acc[i][j][1] += b1 + rv.y;
                    s0 += acc[i][j][0] + acc[i][j][1];
                    q0 += acc[i][j][0] * acc[i][j][0] + acc[i][j][1] * acc[i][j][1];
                }
                if (r1 < M) {
                    float2 rv = *reinterpret_cast<const float2*>(res + (size_t)r1 * D + c);
                    acc[i][j][2] += b0 + rv.x;
                    acc[i][j][3] += b1 + rv.y;
                    s1 += acc[i][j][2] + acc[i][j][3];
                    q1 += acc[i][j][2] * acc[i][j][2] + acc[i][j][3] * acc[i][j][3];
                }
            }
            if (r0 < M) { atomicAdd(&row_s[lr0], s0); atomicAdd(&row_sq[lr0], q0); }
            if (r1 < M) { atomicAdd(&row_s[lr1], s1); atomicAdd(&row_sq[lr1], q1); }
        }
        __syncthreads();
        if (tid < 128) {
            float mu  = row_s[tid] * (1.f / 128.f);
            float var = row_sq[tid] * (1.f / 128.f) - mu * mu;
            row_s[tid]  = mu;
            row_sq[tid] = rsqrtf(var + 1e-5f);
        }
        __syncthreads();
        #pragma unroll
        for (int i = 0; i < 2; i++) {
            int lr0 = wm + i * 16 + (lane >> 2);
            int lr1 = lr0 + 8;
            int r0 = bm + lr0, r1 = bm + lr1;
            float mu0 = row_s[lr0], rs0 = row_sq[lr0];
            float mu1 = row_s[lr1], rs1 = row_sq[lr1];
            #pragma unroll
            for (int j = 0; j < 8; j++) {
                int c = wn + j * 8 + (lane & 3) * 2;
                float g0 = lng[c], g1 = lng[c + 1];
                float bb0 = lnb[c], bb1 = lnb[c + 1];
                if (r0 < M) {
                    float v0 = (acc[i][j][0] - mu0) * rs0 * g0 + bb0;
                    float v1 = (acc[i][j][1] - mu0) * rs0 * g1 + bb1;
                    *reinterpret_cast<float2*>(C + (size_t)r0 * D + c) = make_float2(v0, v1);
                    Cb2[(size_t)r0 * (D >> 1) + (c >> 1)] = packbf(v0, v1);
                }
                if (r1 < M) {
                    float v0 = (acc[i][j][2] - mu1) * rs1 * g0 + bb0;
                    float v1 = (acc[i][j][3] - mu1) * rs1 * g1 + bb1;
                    *reinterpret_cast<float2*>(C + (size_t)r1 * D + c) = make_float2(v0, v1);
                    Cb2[(size_t)r1 * (D >> 1) + (c >> 1)] = packbf(v0, v1);
                }
            }
        }
    }
}

template <int EPI, bool BF16OUT, bool A_BF16>
__global__ __launch_bounds__(256, 2)
void mma_gemm_kernel(const void* __restrict__ A, const uint32_t* __restrict__ Bt,
                     const float* __restrict__ bias, const float* __restrict__ res,
                     float* __restrict__ C, int M, int N, int K) {
    gemm_body<EPI, BF16OUT, A_BF16, false>(A, Bt, bias, res, C, M, N, K,
                                           nullptr, nullptr, nullptr);
}

// fused Q/K/V projection: outputs bf16
__global__ __launch_bounds__(256, 2)
void mma_gemm_qkv_kernel(const float* __restrict__ A,
                         const float* __restrict__ bq, const float* __restrict__ bk,
                         const float* __restrict__ bv, int M) {
    int z = blockIdx.z;
    const uint32_t* Bt = g_wts + (z == 0 ? WQ_OFF : z == 1 ? WK_OFF : WV_OFF);
    const float* bi = (z == 0) ? bq : (z == 1) ? bk : bv;
    float* C = reinterpret_cast<float*>((z == 0) ? g_qb : (z == 1) ? g_kb : g_vb);
    gemm_body<0, true, false, false>(A, Bt, bi, nullptr, C, M, D, D,
                                     nullptr, nullptr, nullptr);
}

// Wo: normalize + GEMM + residual + LayerNorm -> fp32 ln + bf16 lnb
__global__ __launch_bounds__(256, 2)
void mma_gemm_wo_ln_kernel(const float* __restrict__ A,
                           const float* __restrict__ bias, const float* __restrict__ x,
                           const float* __restrict__ lng, const float* __restrict__ lnb,
                           float* __restrict__ C, int M) {
    gemm_body<2, false, false, true>(A, g_wts + WO_OFF, bias, x, C, M, D, D,
                                     lng, lnb, g_lnb);
}

// ---------------- launch ----------------------------------------------------
extern "C" void kernel_launch(void* const* d_in, const int* in_sizes, int n_in,
                              void* d_out, int out_size) {
    const float* x   = (const float*)d_in[0];
    const int*   ei  = (const int*)d_in[1];
    const float* Wq  = (const float*)d_in[2];
    const float* bq  = (const float*)d_in[3];
    const float* Wk  = (const float*)d_in[4];
    const float* bk  = (const float*)d_in[5];
    const float* Wv  = (const float*)d_in[6];
    const float* bv  = (const float*)d_in[7];
    const float* Wo  = (const float*)d_in[8];
    const float* bo  = (const float*)d_in[9];
    const float* lng = (const float*)d_in[10];
    const float* lnb = (const float*)d_in[11];
    const float* W1  = (const float*)d_in[12];
    const float* b1  = (const float*)d_in[13];
    const float* W2  = (const float*)d_in[14];
    const float* b2  = (const float*)d_in[15];

    int N = in_sizes[0] / D;   // 40000
    int E = in_sizes[1] / 2;   // 640000

    void *pagg, *pln, *plnb, *phid, *pwts;
    cudaGetSymbolAddress(&pagg, g_agg);
    cudaGetSymbolAddress(&pln,  g_ln);
    cudaGetSymbolAddress(&plnb, g_lnb);
    cudaGetSymbolAddress(&phid, g_hidden);
    cudaGetSymbolAddress(&pwts, g_wts);

    float* agg = (float*)pagg;
    float* ln  = (float*)pln;

    int mb = (N + 127) / 128;

    // 0. weight convert+transpose to bf16 [n][k]
    wconv_kernel<<<(98304 + 255) / 256, 256>>>(Wq, Wk, Wv, Wo, W1, W2);

    // 1. init accumulators
    init_kernel<<<(N * 32 + 255) / 256, 256>>>(N);

    // 2. fused q/k/v projections
    dim3 gQKV(mb, 1, 3);
    mma_gemm_qkv_kernel<<<gQKV, 256>>>(x, bq, bk, bv, N);

    // 3. fused edge phase
    int eblocks = (E * 32 + 255) / 256;
    edge_fused_kernel<<<eblocks, 256>>>(ei, E);

    // 4. normalize + Wo + residual + LayerNorm -> g_ln (fp32) + g_lnb (bf16)
    mma_gemm_wo_ln_kernel<<<mb, 256>>>(agg, bo, x, lng, lnb, ln, N);

    // 5. MLP: gelu(lnb @ W1 + b1) -> hidden(bf16); hidden @ W2 + b2 + ln -> out
    dim3 gH(mb, HID / 128);
    dim3 gD(mb, 1);
    mma_gemm_kernel<1, true,  true><<<gH, 256>>>(plnb, (uint32_t*)pwts + W1_OFF,
                                                 b1, nullptr, (float*)phid,
                                                 N, HID, D);
    mma_gemm_kernel<2, false, true><<<gD, 256>>>(phid, (uint32_t*)pwts + W2_OFF,
                                                 b2, ln, (float*)d_out,
                                                 N, D, HID);
}

// round 10
// speedup vs baseline: 1.2765x; 1.0160x over previous
#include <cuda_runtime.h>
#include <cuda_bf16.h>
#include <math.h>
#include <stdint.h>

#define NMAX 40000
#define EMAX 640000
#define D    128
#define HID  512

// ---------------- scratch ----------------------------------------------------
__device__ uint32_t g_qb[NMAX * (D / 2)];
__device__ uint32_t g_kb[NMAX * (D / 2)];
__device__ uint32_t g_vb[NMAX * (D / 2)];
__device__ float    g_segsum[NMAX * 4];
__device__ float    g_agg[NMAX * D];
__device__ float    g_ln[NMAX * D];
__device__ uint32_t g_lnb[NMAX * (D / 2)];       // ln in bf16x2
__device__ uint32_t g_hidden[NMAX * (HID / 2)];  // hidden in bf16x2
__device__ uint32_t g_wts[98304];                // all weights bf16, transposed [n][k]

#define WQ_OFF 0
#define WK_OFF 8192
#define WV_OFF 16384
#define WO_OFF 24576
#define W1_OFF 32768
#define W2_OFF 65536

// ---------------- init -------------------------------------------------------
__global__ void init_kernel(int n) {
    int i = blockIdx.x * blockDim.x + threadIdx.x;
    if (i < n * (D / 4)) reinterpret_cast<float4*>(g_agg)[i] =
        make_float4(0.f, 0.f, 0.f, 0.f);
    if (i < n) reinterpret_cast<float4*>(g_segsum)[i] =
        make_float4(0.f, 0.f, 0.f, 0.f);
}

__device__ __forceinline__ uint32_t packbf(float x, float y) {
    __nv_bfloat162 h = __float22bfloat162_rn(make_float2(x, y));
    return *reinterpret_cast<uint32_t*>(&h);
}

// bf16x2 -> float2 via shift/mask (exact, ALU-only)
__device__ __forceinline__ float2 bf2f(uint32_t u) {
    return make_float2(__uint_as_float(u << 16),
                       __uint_as_float(u & 0xffff0000u));
}

// ---------------- weight convert + transpose: W[K,N] fp32 -> Wt[n][k] bf16 ---
__global__ void wconv_kernel(const float* __restrict__ Wq, const float* __restrict__ Wk,
                             const float* __restrict__ Wv, const float* __restrict__ Wo,
                             const float* __restrict__ W1, const float* __restrict__ W2) {
    int i = blockIdx.x * blockDim.x + threadIdx.x;
    if (i >= 98304) return;
    const float* src; int off, Nn, Kk;
    if      (i < WK_OFF) { src = Wq; off = WQ_OFF; Nn = 128; Kk = 128; }
    else if (i < WV_OFF) { src = Wk; off = WK_OFF; Nn = 128; Kk = 128; }
    else if (i < WO_OFF) { src = Wv; off = WV_OFF; Nn = 128; Kk = 128; }
    else if (i < W1_OFF) { src = Wo; off = WO_OFF; Nn = 128; Kk = 128; }
    else if (i < W2_OFF) { src = W1; off = W1_OFF; Nn = 512; Kk = 128; }
    else                 { src = W2; off = W2_OFF; Nn = 128; Kk = 512; }
    int idx = i - off;
    int kh  = Kk >> 1;
    int n   = idx / kh;
    int kp  = idx % kh;
    float v0 = src[(size_t)(2 * kp)     * Nn + n];
    float v1 = src[(size_t)(2 * kp + 1) * Nn + n];
    g_wts[i] = packbf(v0, v1);
}

// ---------------- fused edge pass: 16 lanes per edge, uint4 gathers ----------
// Scores std ~0.05 -> softmax without max-subtract is exact (shift-invariant).
__global__ void edge_fused_kernel(const int* __restrict__ ei, int E) {
    int gtid = blockIdx.x * blockDim.x + threadIdx.x;
    int e  = gtid >> 4;          // 2 edges per warp
    int sl = threadIdx.x & 15;   // sublane within edge group
    if (e >= E) return;
    int src = ei[e];
    int dst = ei[E + e];

    // q[dst], k[src] rows: 64 u32 each; 16 lanes x uint4
    uint4 qp = reinterpret_cast<const uint4*>(g_qb)[dst * 16 + sl];
    uint4 kp = reinterpret_cast<const uint4*>(g_kb)[src * 16 + sl];

    float2 q0 = bf2f(qp.x), q1 = bf2f(qp.y), q2 = bf2f(qp.z), q3 = bf2f(qp.w);
    float2 k0 = bf2f(kp.x), k1 = bf2f(kp.y), k2 = bf2f(kp.z), k3 = bf2f(kp.w);
    float p = q0.x * k0.x + q0.y * k0.y + q1.x * k1.x + q1.y * k1.y
            + q2.x * k2.x + q2.y * k2.y + q3.x * k3.x + q3.y * k3.y;
    // reduce within 4-lane head group (head = sl>>2)
    p += __shfl_xor_sync(0xffffffffu, p, 1);
    p += __shfl_xor_sync(0xffffffffu, p, 2);
    float ex = __expf(p * 0.17677669529663687f);  // 1/sqrt(32)

    if ((sl & 3) == 0) atomicAdd(&g_segsum[dst * 4 + (sl >> 2)], ex);

    uint4 vp = reinterpret_cast<const uint4*>(g_vb)[src * 16 + sl];
    float2 v0 = bf2f(vp.x), v1 = bf2f(vp.y), v2 = bf2f(vp.z), v3 = bf2f(vp.w);
    float* pd = g_agg + dst * 128 + sl * 8;
    asm volatile("red.global.add.v4.f32 [%0], {%1, %2, %3, %4};"
                 :: "l"(pd), "f"(v0.x * ex), "f"(v0.y * ex),
                    "f"(v1.x * ex), "f"(v1.y * ex) : "memory");
    asm volatile("red.global.add.v4.f32 [%0], {%1, %2, %3, %4};"
                 :: "l"(pd + 4), "f"(v2.x * ex), "f"(v2.y * ex),
                    "f"(v3.x * ex), "f"(v3.y * ex) : "memory");
}

__device__ __forceinline__ float gelu_tanh(float x) {
    float u = 0.7978845608028654f * (x + 0.044715f * x * x * x);
    float e = __expf(2.f * u);
    return x * e / (e + 1.f);
}

#define AP 12   // u32 pitch per smem row

// ---------------- bf16 m16n8k16 GEMM body ------------------------------------
template <int EPI, bool BF16OUT, bool A_BF16, bool NORM>
__device__ __forceinline__
void gemm_body(const void* __restrict__ A, const uint32_t* __restrict__ Bt,
               const float* __restrict__ bias, const float* __restrict__ res,
               float* __restrict__ C, int M, int N, int K,
               const float* __restrict__ lng, const float* __restrict__ lnb,
               uint32_t* __restrict__ Cb2) {
    __shared__ uint32_t As[2][128 * AP];
    __shared__ uint32_t Bs[2][128 * AP];
    __shared__ float row_s[128];
    __shared__ float row_sq[128];

    const int tid  = threadIdx.x;
    const int lane = tid & 31;
    const int wid  = tid >> 5;
    const int bm   = blockIdx.x * 128;
    const int bn   = blockIdx.y * 128;
    const int wm   = (wid & 3) * 32;
    const int wn   = (wid >> 2) * 64;
    const int khalf = tid & 1;
    const int kh    = K >> 1;

    const int b_n = tid >> 1;

    float rcp0[4], rcp1[4];
    float4 a_reg0, a_reg1;
    uint4  a_regb;
    int ar0, ar1, arb;
    if (A_BF16) {
        arb = min(bm + (tid >> 1), M - 1);
    } else {
        ar0 = min(bm + (tid >> 2),      M - 1);
        ar1 = min(bm + (tid >> 2) + 64, M - 1);
    }
    const int a_col = (tid & 3) * 4;

    if (NORM) {
        if (tid < 128) { row_s[tid] = 0.f; row_sq[tid] = 0.f; }
        float4 ss0 = *reinterpret_cast<const float4*>(g_segsum + (size_t)ar0 * 4);
        float4 ss1 = *reinterpret_cast<const float4*>(g_segsum + (size_t)ar1 * 4);
        rcp0[0] = ss0.x > 0.f ? __frcp_rn(ss0.x) : 0.f;
        rcp0[1] = ss0.y > 0.f ? __frcp_rn(ss0.y) : 0.f;
        rcp0[2] = ss0.z > 0.f ? __frcp_rn(ss0.z) : 0.f;
        rcp0[3] = ss0.w > 0.f ? __frcp_rn(ss0.w) : 0.f;
        rcp1[0] = ss1.x > 0.f ? __frcp_rn(ss1.x) : 0.f;
        rcp1[1] = ss1.y > 0.f ? __frcp_rn(ss1.y) : 0.f;
        rcp1[2] = ss1.z > 0.f ? __frcp_rn(ss1.z) : 0.f;
        rcp1[3] = ss1.w > 0.f ? __frcp_rn(ss1.w) : 0.f;
    }

    float acc[2][8][4];
    #pragma unroll
    for (int i = 0; i < 2; i++)
        #pragma unroll
        for (int j = 0; j < 8; j++)
            #pragma unroll
            for (int c = 0; c < 4; c++) acc[i][j][c] = 0.f;

    if (A_BF16) {
        a_regb = *reinterpret_cast<const uint4*>(
            reinterpret_cast<const uint32_t*>(A) + (size_t)arb * (K >> 1) + khalf * 4);
    } else {
        a_reg0 = *reinterpret_cast<const float4*>(
            reinterpret_cast<const float*>(A) + (size_t)ar0 * K + a_col);
        a_reg1 = *reinterpret_cast<const float4*>(
            reinterpret_cast<const float*>(A) + (size_t)ar1 * K + a_col);
    }
    uint4 b_regb = *reinterpret_cast<const uint4*>(
        Bt + (size_t)(bn + b_n) * kh + khalf * 4);

    const int nIter = K >> 4;
    for (int it = 0; it < nIter; it++) {
        const int cur = it & 1;
        if (A_BF16) {
            *reinterpret_cast<uint4*>(&As[cur][(tid >> 1) * AP + khalf * 4]) = a_regb;
        } else {
            float n0 = 1.f, n1 = 1.f;
            if (NORM) { n0 = rcp0[it >> 1]; n1 = rcp1[it >> 1]; }
            uint2 pa = make_uint2(packbf(a_reg0.x * n0, a_reg0.y * n0),
                                  packbf(a_reg0.z * n0, a_reg0.w * n0));
            *reinterpret_cast<uint2*>(&As[cur][(tid >> 2) * AP + (tid & 3) * 2]) = pa;
            uint2 pb = make_uint2(packbf(a_reg1.x * n1, a_reg1.y * n1),
                                  packbf(a_reg1.z * n1, a_reg1.w * n1));
            *reinterpret_cast<uint2*>(&As[cur][((tid >> 2) + 64) * AP + (tid & 3) * 2]) = pb;
        }
        *reinterpret_cast<uint4*>(&Bs[cur][b_n * AP + khalf * 4]) = b_regb;
        __syncthreads();

        if (it + 1 < nIter) {
            int kn = (it + 1) << 4;
            if (A_BF16) {
                a_regb = *reinterpret_cast<const uint4*>(
                    reinterpret_cast<const uint32_t*>(A) +
                    (size_t)arb * (K >> 1) + (kn >> 1) + khalf * 4);
            } else {
                a_reg0 = *reinterpret_cast<const float4*>(
                    reinterpret_cast<const float*>(A) + (size_t)ar0 * K + kn + a_col);
                a_reg1 = *reinterpret_cast<const float4*>(
                    reinterpret_cast<const float*>(A) + (size_t)ar1 * K + kn + a_col);
            }
            b_regb = *reinterpret_cast<const uint4*>(
                Bt + (size_t)(bn + b_n) * kh + (kn >> 1) + khalf * 4);
        }

        uint32_t af[2][4];
        #pragma unroll
        for (int i = 0; i < 2; i++) {
            int m = wm + i * 16 + (lane >> 2);
            int c = lane & 3;
            af[i][0] = As[cur][m * AP + c];
            af[i][1] = As[cur][(m + 8) * AP + c];
            af[i][2] = As[cur][m * AP + c + 4];
            af[i][3] = As[cur][(m + 8) * AP + c + 4];
        }
        uint32_t bfr[8][2];
        #pragma unroll
        for (int j = 0; j < 8; j++) {
            int n = wn + j * 8 + (lane >> 2);
            int c = lane & 3;
            bfr[j][0] = Bs[cur][n * AP + c];
            bfr[j][1] = Bs[cur][n * AP + c + 4];
        }
        #pragma unroll
        for (int i = 0; i < 2; i++)
            #pragma unroll
            for (int j = 0; j < 8; j++) {
                asm volatile(
                    "mma.sync.aligned.m16n8k16.row.col.f32.bf16.bf16.f32 "
                    "{%0,%1,%2,%3}, {%4,%5,%6,%7}, {%8,%9}, {%0,%1,%2,%3};"
                    : "+f"(acc[i][j][0]), "+f"(acc[i][j][1]),
                      "+f"(acc[i][j][2]), "+f"(acc[i][j][3])
                    : "r"(af[i][0]), "r"(af[i][1]), "r"(af[i][2]), "r"(af[i][3]),
                      "r"(bfr[j][0]), "r"(bfr[j][1]));
            }
        __syncthreads();
    }

    if (!NORM) {
        uint32_t* Cb = reinterpret_cast<uint32_t*>(C);
        #pragma unroll
        for (int i = 0; i < 2; i++) {
            int r0 = bm + wm + i * 16 + (lane >> 2);
            int r1 = r0 + 8;
            #pragma unroll
            for (int j = 0; j < 8; j++) {
                int c = bn + wn + j * 8 + (lane & 3) * 2;
                float b0 = bias[c], b1 = bias[c + 1];
                float v00 = acc[i][j][0] + b0, v01 = acc[i][j][1] + b1;
                float v10 = acc[i][j][2] + b0, v11 = acc[i][j][3] + b1;
                if (EPI == 1) {
                    v00 = gelu_tanh(v00); v01 = gelu_tanh(v01);
                    v10 = gelu_tanh(v10); v11 = gelu_tanh(v11);
                }
                if (r0 < M) {
                    if (EPI == 2) {
                        float2 rv = *reinterpret_cast<const float2*>(res + (size_t)r0 * N + c);
                        v00 += rv.x; v01 += rv.y;
                    }
                    if (BF16OUT)
                        Cb[(size_t)r0 * (N >> 1) + (c >> 1)] = packbf(v00, v01);
                    else
                        *reinterpret_cast<float2*>(C + (size_t)r0 * N + c) = make_float2(v00, v01);
                }
                if (r1 < M) {
                    if (EPI == 2) {
                        float2 rv = *reinterpret_cast<const float2*>(res + (size_t)r1 * N + c);
                        v10 += rv.x; v11 += rv.y;
                    }
                    if (BF16OUT)
                        Cb[(size_t)r1 * (N >> 1) + (c >> 1)] = packbf(v10, v11);
                    else
                        *reinterpret_cast<float2*>(C + (size_t)r1 * N + c) = make_float2(v10, v11);
                }
            }
        }
    } else {
        #pragma unroll
        for (int i = 0; i < 2; i++) {
            int lr0 = wm + i * 16 + (lane >> 2);
            int lr1 = lr0 + 8;
            int r0 = bm + lr0, r1 = bm + lr1;
            float s0 = 0.f, q0 = 0.f, s1 = 0.f, q1 = 0.f;
            #pragma unroll
            for (int j = 0; j < 8; j++) {
                int c = wn + j * 8 + (lane & 3) * 2;
                float b0 = bias[c], b1 = bias[c + 1];
                if (r0 < M) {
                    float2 rv = *reinterpret_cast<const float2*>(res + (size_t)r0 * D + c);
                    acc[i][j][0] += b0 + rv.x;
                    acc[i][j][1] += b1 + rv.y;
                    s0 += acc[i][j][0] + acc[i][j][1];
                    q0 += acc[i][j][0] * acc[i][j][0] + acc[i][j][1] * acc[i][j][1];
                }
                if (r1 < M) {
                    float2 rv = *reinterpret_cast<const float2*>(res + (size_t)r1 * D + c);
                    acc[i][j][2] += b0 + rv.x;
                    acc[i][j][3] += b1 + rv.y;
                    s1 += acc[i][j][2] + acc[i][j][3];
                    q1 += acc[i][j][2] * acc[i][j][2] + acc[i][j][3] * acc[i][j][3];
                }
            }
            if (r0 < M) { atomicAdd(&row_s[lr0], s0); atomicAdd(&row_sq[lr0], q0); }
            if (r1 < M) { atomicAdd(&row_s[lr1], s1); atomicAdd(&row_sq[lr1], q1); }
        }
        __syncthreads();
        if (tid < 128) {
            float mu  = row_s[tid] * (1.f / 128.f);
            float var = row_sq[tid] * (1.f / 128.f) - mu * mu;
            row_s[tid]  = mu;
            row_sq[tid] = rsqrtf(var + 1e-5f);
        }
        __syncthreads();
        #pragma unroll
        for (int i = 0; i < 2; i++) {
            int lr0 = wm + i * 16 + (lane >> 2);
            int lr1 = lr0 + 8;
            int r0 = bm + lr0, r1 = bm + lr1;
            float mu0 = row_s[lr0], rs0 = row_sq[lr0];
            float mu1 = row_s[lr1], rs1 = row_sq[lr1];
            #pragma unroll
            for (int j = 0; j < 8; j++) {
                int c = wn + j * 8 + (lane & 3) * 2;
                float g0 = lng[c], g1 = lng[c + 1];
                float bb0 = lnb[c], bb1 = lnb[c + 1];
                if (r0 < M) {
                    float v0 = (acc[i][j][0] - mu0) * rs0 * g0 + bb0;
                    float v1 = (acc[i][j][1] - mu0) * rs0 * g1 + bb1;
                    *reinterpret_cast<float2*>(C + (size_t)r0 * D + c) = make_float2(v0, v1);
                    Cb2[(size_t)r0 * (D >> 1) + (c >> 1)] = packbf(v0, v1);
                }
                if (r1 < M) {
                    float v0 = (acc[i][j][2] - mu1) * rs1 * g0 + bb0;
                    float v1 = (acc[i][j][3] - mu1) * rs1 * g1 + bb1;
                    *reinterpret_cast<float2*>(C + (size_t)r1 * D + c) = make_float2(v0, v1);
                    Cb2[(size_t)r1 * (D >> 1) + (c >> 1)] = packbf(v0, v1);
                }
            }
        }
    }
}

template <int EPI, bool BF16OUT, bool A_BF16>
__global__ __launch_bounds__(256, 2)
void mma_gemm_kernel(const void* __restrict__ A, const uint32_t* __restrict__ Bt,
                     const float* __restrict__ bias, const float* __restrict__ res,
                     float* __restrict__ C, int M, int N, int K) {
    gemm_body<EPI, BF16OUT, A_BF16, false>(A, Bt, bias, res, C, M, N, K,
                                           nullptr, nullptr, nullptr);
}

__global__ __launch_bounds__(256, 2)
void mma_gemm_qkv_kernel(const float* __restrict__ A,
                         const float* __restrict__ bq, const float* __restrict__ bk,
                         const float* __restrict__ bv, int M) {
    int z = blockIdx.z;
    const uint32_t* Bt = g_wts + (z == 0 ? WQ_OFF : z == 1 ? WK_OFF : WV_OFF);
    const float* bi = (z == 0) ? bq : (z == 1) ? bk : bv;
    float* C = reinterpret_cast<float*>((z == 0) ? g_qb : (z == 1) ? g_kb : g_vb);
    gemm_body<0, true, false, false>(A, Bt, bi, nullptr, C, M, D, D,
                                     nullptr, nullptr, nullptr);
}

__global__ __launch_bounds__(256, 2)
void mma_gemm_wo_ln_kernel(const float* __restrict__ A,
                           const float* __restrict__ bias, const float* __restrict__ x,
                           const float* __restrict__ lng, const float* __restrict__ lnb,
                           float* __restrict__ C, int M) {
    gemm_body<2, false, false, true>(A, g_wts + WO_OFF, bias, x, C, M, D, D,
                                     lng, lnb, g_lnb);
}

// ---------------- launch ----------------------------------------------------
extern "C" void kernel_launch(void* const* d_in, const int* in_sizes, int n_in,
                              void* d_out, int out_size) {
    const float* x   = (const float*)d_in[0];
    const int*   ei  = (const int*)d_in[1];
    const float* Wq  = (const float*)d_in[2];
    const float* bq  = (const float*)d_in[3];
    const float* Wk  = (const float*)d_in[4];
    const float* bk  = (const float*)d_in[5];
    const float* Wv  = (const float*)d_in[6];
    const float* bv  = (const float*)d_in[7];
    const float* Wo  = (const float*)d_in[8];
    const float* bo  = (const float*)d_in[9];
    const float* lng = (const float*)d_in[10];
    const float* lnb = (const float*)d_in[11];
    const float* W1  = (const float*)d_in[12];
    const float* b1  = (const float*)d_in[13];
    const float* W2  = (const float*)d_in[14];
    const float* b2  = (const float*)d_in[15];

    int N = in_sizes[0] / D;   // 40000
    int E = in_sizes[1] / 2;   // 640000

    void *pagg, *pln, *plnb, *phid, *pwts;
    cudaGetSymbolAddress(&pagg, g_agg);
    cudaGetSymbolAddress(&pln,  g_ln);
    cudaGetSymbolAddress(&plnb, g_lnb);
    cudaGetSymbolAddress(&phid, g_hidden);
    cudaGetSymbolAddress(&pwts, g_wts);

    float* agg = (float*)pagg;
    float* ln  = (float*)pln;

    int mb = (N + 127) / 128;

    // 0. weight convert+transpose
    wconv_kernel<<<(98304 + 255) / 256, 256>>>(Wq, Wk, Wv, Wo, W1, W2);

    // 1. init accumulators
    init_kernel<<<(N * 32 + 255) / 256, 256>>>(N);

    // 2. fused q/k/v projections
    dim3 gQKV(mb, 1, 3);
    mma_gemm_qkv_kernel<<<gQKV, 256>>>(x, bq, bk, bv, N);

    // 3. fused edge phase: 16 lanes/edge
    int eblocks = (E * 16 + 255) / 256;
    edge_fused_kernel<<<eblocks, 256>>>(ei, E);

    // 4. normalize + Wo + residual + LayerNorm -> g_ln + g_lnb
    mma_gemm_wo_ln_kernel<<<mb, 256>>>(agg, bo, x, lng, lnb, ln, N);

    // 5. MLP
    dim3 gH(mb, HID / 128);
    dim3 gD(mb, 1);
    mma_gemm_kernel<1, true,  true><<<gH, 256>>>(plnb, (uint32_t*)pwts + W1_OFF,
                                                 b1, nullptr, (float*)phid,
                                                 N, HID, D);
    mma_gemm_kernel<2, false, true><<<gD, 256>>>(phid, (uint32_t*)pwts + W2_OFF,
                                                 b2, ln, (float*)d_out,
                                                 N, D, HID);
}